// round 12
// baseline (speedup 1.0000x reference)
#include <cuda_runtime.h>
#include <cuda_bf16.h>
#include <cstdint>

// ---------------------------------------------------------------------------
// RGCN forward. CSR gather-mean (warp-per-row, bf16, multi-job), pipelined
// bf16 HMMA GEMMs: BK=64, 3-stage cp.async, ldmatrix with register fragment
// double-buffering, staged epilogues. P=100000, A=50000, IN=128, H=256, OUT=349
// ---------------------------------------------------------------------------

#define P_N   100000
#define A_N   50000
#define IN_C  128
#define H_C   256
#define OUT_C 349
#define EW_MAX 600000
#define EC_MAX 1000000
#define NB_P  98
#define NB_A  49

// bf16 feature buffers
__device__ __nv_bfloat16 g_hp  [(size_t)P_N * H_C];
__device__ __nv_bfloat16 g_outp[(size_t)P_N * H_C];
__device__ __nv_bfloat16 g_outa[(size_t)A_N * H_C];
__device__ __nv_bfloat16 g_aggA[(size_t)P_N * H_C];
__device__ __nv_bfloat16 g_aggB[(size_t)P_N * H_C];
__device__ __nv_bfloat16 g_aggC[(size_t)A_N * H_C];
__device__ __nv_bfloat16 g_emba[(size_t)A_N * H_C];
__device__ __nv_bfloat16 g_xb  [(size_t)P_N * IN_C];

// bf16 weights (padded to Npad columns)
__device__ __nv_bfloat16 g_wlin [IN_C * H_C];
__device__ __nv_bfloat16 g_w0rp [H_C * H_C];
__device__ __nv_bfloat16 g_w0ra [H_C * H_C];
__device__ __nv_bfloat16 g_w0w  [H_C * H_C];
__device__ __nv_bfloat16 g_w0c  [H_C * H_C];
__device__ __nv_bfloat16 g_w0r  [H_C * H_C];
__device__ __nv_bfloat16 g_w1rt [H_C * 352];
__device__ __nv_bfloat16 g_w1w  [H_C * 352];
__device__ __nv_bfloat16 g_w1c  [H_C * 352];

// CSR scratch
__device__ int g_cntW[P_N], g_cntC[P_N], g_cntR[A_N];
__device__ int g_rpW[P_N + 1], g_rpC[P_N + 1], g_rpR[A_N + 1];
__device__ int g_nxW[P_N], g_nxC[P_N], g_nxR[A_N];
__device__ int g_csW[EW_MAX], g_csC[EC_MAX], g_csR[EW_MAX];
__device__ int g_bsum[256];

// ---------------------------------------------------------------------------
__global__ void fill3_kernel(int4* a, int na4, int4* b, int nb4, int4* c, int nc4) {
    int i = blockIdx.x * blockDim.x + threadIdx.x;
    int4 z = make_int4(0, 0, 0, 0);
    if (i < na4) a[i] = z;
    else if (i < na4 + nb4) b[i - na4] = z;
    else if (i < na4 + nb4 + nc4) c[i - na4 - nb4] = z;
}

__global__ void count3_kernel(const int* __restrict__ wdst, int EW, int* __restrict__ cntW,
                              const int* __restrict__ cdst, int EC, int* __restrict__ cntC,
                              const int* __restrict__ rdst, int ER, int* __restrict__ cntR) {
    int i = blockIdx.x * blockDim.x + threadIdx.x;
    if (i < EW) atomicAdd(&cntW[wdst[i]], 1);
    else if (i < EW + EC) atomicAdd(&cntC[cdst[i - EW]], 1);
    else if (i < EW + EC + ER) atomicAdd(&cntR[rdst[i - EW - EC]], 1);
}

// ---------------------------------------------------------------------------
#define SCB 1024

__global__ void scan1_3_kernel(const int* __restrict__ cW, const int* __restrict__ cC,
                               const int* __restrict__ cR, int* __restrict__ bsum) {
    int b = blockIdx.x;
    const int* cnt; int n, base, lb;
    if (b < NB_P)           { cnt = cW; n = P_N; base = 0;        lb = b; }
    else if (b < 2 * NB_P)  { cnt = cC; n = P_N; base = NB_P;     lb = b - NB_P; }
    else                    { cnt = cR; n = A_N; base = 2 * NB_P; lb = b - 2 * NB_P; }
    __shared__ int sh[SCB];
    int tid = threadIdx.x;
    int i = lb * SCB + tid;
    sh[tid] = (i < n) ? cnt[i] : 0;
    __syncthreads();
    for (int off = SCB / 2; off; off >>= 1) {
        if (tid < off) sh[tid] += sh[tid + off];
        __syncthreads();
    }
    if (!tid) bsum[base + lb] = sh[0];
}

__global__ void scan2_3_kernel(int* __restrict__ bsum) {
    __shared__ int sh[SCB];
    int tid = threadIdx.x;
    int bases[3] = {0, NB_P, 2 * NB_P};
    int nbs[3]   = {NB_P, NB_P, NB_A};
#pragma unroll
    for (int r = 0; r < 3; r++) {
        int nb = nbs[r];
        int v = (tid < nb) ? bsum[bases[r] + tid] : 0;
        sh[tid] = v;
        __syncthreads();
        for (int off = 1; off < SCB; off <<= 1) {
            int a = (tid >= off) ? sh[tid - off] : 0;
            __syncthreads();
            sh[tid] += a;
            __syncthreads();
        }
        if (tid < nb) bsum[bases[r] + tid] = sh[tid] - v;
        __syncthreads();
    }
}

__global__ void scan3_3_kernel(const int* __restrict__ cW, const int* __restrict__ cC,
                               const int* __restrict__ cR, const int* __restrict__ bsum,
                               int* __restrict__ rpW, int* __restrict__ rpC, int* __restrict__ rpR,
                               int* __restrict__ nxW, int* __restrict__ nxC, int* __restrict__ nxR) {
    int b = blockIdx.x;
    const int* cnt; int n, base, lb; int *rowptr, *nextp;
    if (b < NB_P)          { cnt = cW; n = P_N; base = 0;        lb = b;            rowptr = rpW; nextp = nxW; }
    else if (b < 2 * NB_P) { cnt = cC; n = P_N; base = NB_P;     lb = b - NB_P;     rowptr = rpC; nextp = nxC; }
    else                   { cnt = cR; n = A_N; base = 2 * NB_P; lb = b - 2 * NB_P; rowptr = rpR; nextp = nxR; }
    __shared__ int sh[SCB];
    int tid = threadIdx.x;
    int i = lb * SCB + tid;
    int v = (i < n) ? cnt[i] : 0;
    sh[tid] = v;
    __syncthreads();
    for (int off = 1; off < SCB; off <<= 1) {
        int a = (tid >= off) ? sh[tid - off] : 0;
        __syncthreads();
        sh[tid] += a;
        __syncthreads();
    }
    int excl = sh[tid] - v + bsum[base + lb];
    if (i < n) { rowptr[i] = excl; nextp[i] = excl; }
    if (i == n - 1) rowptr[n] = excl + v;
}

__global__ void build3_kernel(const int* __restrict__ wsrc, const int* __restrict__ wdst, int EW,
                              int* __restrict__ nxW, int* __restrict__ csW,
                              const int* __restrict__ csrc, const int* __restrict__ cdst, int EC,
                              int* __restrict__ nxC, int* __restrict__ csC,
                              const int* __restrict__ rsrc, const int* __restrict__ rdst, int ER,
                              int* __restrict__ nxR, int* __restrict__ csR) {
    int i = blockIdx.x * blockDim.x + threadIdx.x;
    if (i < EW) {
        int p = atomicAdd(&nxW[wdst[i]], 1); csW[p] = wsrc[i];
    } else if (i < EW + EC) {
        int k = i - EW;
        int p = atomicAdd(&nxC[cdst[k]], 1); csC[p] = csrc[k];
    } else if (i < EW + EC + ER) {
        int k = i - EW - EC;
        int p = atomicAdd(&nxR[rdst[k]], 1); csR[p] = rsrc[k];
    }
}

// ---------------------------------------------------------------------------
__global__ void f2b_all_kernel(const float4* __restrict__ in0, uint2* __restrict__ out0, int n0,
                               const float4* __restrict__ in1, uint2* __restrict__ out1, int n1) {
    int i = blockIdx.x * blockDim.x + threadIdx.x;
    const float4* in; uint2* out; int k;
    if (i < n0)           { in = in0; out = out0; k = i; }
    else if (i < n0 + n1) { in = in1; out = out1; k = i - n0; }
    else return;
    float4 v = in[k];
    __nv_bfloat162 a = __floats2bfloat162_rn(v.x, v.y);
    __nv_bfloat162 b = __floats2bfloat162_rn(v.z, v.w);
    uint2 o;
    o.x = *(uint32_t*)&a;
    o.y = *(uint32_t*)&b;
    out[k] = o;
}

struct W2B {
    const float* src[9];
    __nv_bfloat16* dst[9];
    int N[9];
    int Npad[9];
    int cum[10];
};
__global__ void w2b_all_kernel(W2B b) {
    int i = blockIdx.x * blockDim.x + threadIdx.x;
    if (i >= b.cum[9]) return;
    int r = 0;
#pragma unroll
    for (int q = 0; q < 8; q++) if (i >= b.cum[q + 1]) r = q + 1;
    int local = i - b.cum[r];
    int Npad = b.Npad[r], N = b.N[r];
    int k = local / Npad, c = local - k * Npad;
    b.dst[r][local] = __float2bfloat16(c < N ? b.src[r][k * N + c] : 0.f);
}

// ---------------------------------------------------------------------------
// Multi-job gather-mean. One warp per dst row; lane owns 8 channels (uint4).
// ---------------------------------------------------------------------------
struct GJob {
    const __nv_bfloat16* feat;
    const int* rowptr;
    const int* csr;
    __nv_bfloat16* agg;
};
struct GMulti { GJob j[3]; int cum[4]; };

__device__ __forceinline__ void acc8(float* s, uint4 u) {
    float2 f0 = __bfloat1622float2(*(__nv_bfloat162*)&u.x);
    float2 f1 = __bfloat1622float2(*(__nv_bfloat162*)&u.y);
    float2 f2 = __bfloat1622float2(*(__nv_bfloat162*)&u.z);
    float2 f3 = __bfloat1622float2(*(__nv_bfloat162*)&u.w);
    s[0] += f0.x; s[1] += f0.y; s[2] += f1.x; s[3] += f1.y;
    s[4] += f2.x; s[5] += f2.y; s[6] += f3.x; s[7] += f3.y;
}

__global__ void gather_multi_kernel(GMulti g) {
    int group = blockIdx.x * 8 + (threadIdx.x >> 5);
    int lane  = threadIdx.x & 31;
    if (group >= g.cum[3]) return;
    int r = (group >= g.cum[1]) + (group >= g.cum[2]);
    const __nv_bfloat16* __restrict__ feat = g.j[r].feat;
    const int* __restrict__ rowptr = g.j[r].rowptr;
    const int* __restrict__ csr    = g.j[r].csr;
    __nv_bfloat16* __restrict__ agg = g.j[r].agg;
    int row = group - g.cum[r];

    int beg = rowptr[row], end = rowptr[row + 1];
    int c8 = lane * 8;

    float s[8] = {0.f, 0.f, 0.f, 0.f, 0.f, 0.f, 0.f, 0.f};
    int i = beg;
    for (; i + 1 < end; i += 2) {
        int sa = csr[i];
        int sb = csr[i + 1];
        uint4 ua = *(const uint4*)&feat[(size_t)sa * H_C + c8];
        uint4 ub = *(const uint4*)&feat[(size_t)sb * H_C + c8];
        acc8(s, ua);
        acc8(s, ub);
    }
    if (i < end) {
        uint4 ua = *(const uint4*)&feat[(size_t)csr[i] * H_C + c8];
        acc8(s, ua);
    }
    float inv = (end > beg) ? 1.0f / (float)(end - beg) : 0.f;
    __nv_bfloat162 o0 = __floats2bfloat162_rn(s[0] * inv, s[1] * inv);
    __nv_bfloat162 o1 = __floats2bfloat162_rn(s[2] * inv, s[3] * inv);
    __nv_bfloat162 o2 = __floats2bfloat162_rn(s[4] * inv, s[5] * inv);
    __nv_bfloat162 o3 = __floats2bfloat162_rn(s[6] * inv, s[7] * inv);
    uint4 o;
    o.x = *(uint32_t*)&o0; o.y = *(uint32_t*)&o1;
    o.z = *(uint32_t*)&o2; o.w = *(uint32_t*)&o3;
    *(uint4*)&agg[(size_t)row * H_C + c8] = o;
}

// ---------------------------------------------------------------------------
// Pipelined fused multi-segment bf16 GEMM, BK=64, 3-stage cp.async,
// register fragment double-buffer, staged epilogue.
// ---------------------------------------------------------------------------
#define BM 128
#define BN 128
#define BK 64
#define PK 72
#define PN 136
#define A_BYTES (BM * PK * 2)
#define B_BYTES (BK * PN * 2)
#define STAGE_BYTES (A_BYTES + B_BYTES)     // 35840
#define NSTAGE 3
#define GEMM_SMEM (NSTAGE * STAGE_BYTES)    // 107520

struct GemmParams {
    const __nv_bfloat16* A[3];
    const __nv_bfloat16* B[3];
    int          K[3];
    int          nseg;
    const float* bias;
    void*        C;
    int          M, N, Npad;
};

__device__ __forceinline__ void cp16(uint32_t dst, const void* src, bool pred) {
    int sz = pred ? 16 : 0;
    asm volatile("cp.async.cg.shared.global [%0], [%1], 16, %2;"
                 :: "r"(dst), "l"(src), "r"(sz));
}

template<bool RELU, bool OUTBF16>
__device__ __forceinline__ void gemm_body(const GemmParams& p, int by) {
    extern __shared__ __align__(16) unsigned char smem_raw[];

    const int t    = threadIdx.x;
    const int lane = t & 31;
    const int w    = t >> 5;
    const int wm   = w & 1;
    const int wn   = w >> 1;
    const int g    = lane >> 2;
    const int tq   = lane & 3;
    const int row0 = by * BM;
    const int col0 = blockIdx.x * BN;
    const int M = p.M, N = p.N, Npad = p.Npad;
    const int nseg = p.nseg;

    const int kt0 = p.K[0] >> 6;
    const int kt1 = (nseg > 1) ? (p.K[1] >> 6) : 0;
    const int kt2 = (nseg > 2) ? (p.K[2] >> 6) : 0;
    const int total = kt0 + kt1 + kt2;

    const uint32_t smBase = (uint32_t)__cvta_generic_to_shared(smem_raw);

    const uint32_t aBase = smBase +
        (uint32_t)(((wm * 64 + (lane & 15)) * PK + ((lane >> 4) << 3)) << 1);
    const uint32_t bBase = smBase + A_BYTES +
        (uint32_t)(((lane & 15) * PN + wn * 32 + ((lane >> 4) << 3)) << 1);

    float acc[4][4][4];
#pragma unroll
    for (int i = 0; i < 4; i++)
#pragma unroll
        for (int j = 0; j < 4; j++)
#pragma unroll
            for (int v = 0; v < 4; v++) acc[i][j][v] = 0.f;

    auto issue = [&](int ti) {
        int s = 0, rem = ti;
        if (rem >= kt0)           { rem -= kt0; s = 1; }
        if (s == 1 && rem >= kt1) { rem -= kt1; s = 2; }
        int k0 = rem * BK;
        const __nv_bfloat16* A = p.A[s];
        const __nv_bfloat16* B = p.B[s];
        int K = p.K[s];
        uint32_t sb = smBase + (uint32_t)((ti % NSTAGE) * STAGE_BYTES);
#pragma unroll
        for (int it = 0; it < 4; it++) {
            int idx = t + it * 256;
            int r   = idx >> 3;
            int c8  = (idx & 7) * 8;
            int gr  = row0 + r;
            bool ok = (gr < M);
            int  sr = ok ? gr : 0;
            uint32_t dst = sb + (uint32_t)((r * PK + c8) << 1);
            cp16(dst, A + (size_t)sr * K + k0 + c8, ok);
        }
#pragma unroll
        for (int it = 0; it < 4; it++) {
            int idx = t + it * 256;
            int kr  = idx >> 4;
            int c8  = (idx & 15) * 8;
            int gc  = col0 + c8;
            bool ok = (gc < Npad);
            int  sc = ok ? gc : 0;
            uint32_t dst = sb + A_BYTES + (uint32_t)((kr * PN + c8) << 1);
            cp16(dst, B + (size_t)(k0 + kr) * Npad + sc, ok);
        }
        asm volatile("cp.async.commit_group;");
    };

    // fragment loader for one k16 step into the given buffers
    auto load_frags = [&](uint32_t so, int ko, uint32_t (*af)[4], uint32_t (*bf)[4]) {
#pragma unroll
        for (int i = 0; i < 4; i++) {
            uint32_t addr = aBase + so + (uint32_t)(((i * 16) * PK + ko) << 1);
            asm volatile("ldmatrix.sync.aligned.m8n8.x4.shared.b16 {%0,%1,%2,%3}, [%4];"
                         : "=r"(af[i][0]), "=r"(af[i][1]), "=r"(af[i][2]), "=r"(af[i][3])
                         : "r"(addr));
        }
#pragma unroll
        for (int jj = 0; jj < 2; jj++) {
            uint32_t addr = bBase + so + (uint32_t)((ko * PN + jj * 16) << 1);
            asm volatile("ldmatrix.sync.aligned.m8n8.x4.trans.shared.b16 {%0,%1,%2,%3}, [%4];"
                         : "=r"(bf[jj][0]), "=r"(bf[jj][1]), "=r"(bf[jj][2]), "=r"(bf[jj][3])
                         : "r"(addr));
        }
    };

    issue(0);
    if (total > 1) issue(1);

    uint32_t afr[2][4][4];
    uint32_t bfr[2][2][4];

    for (int ti = 0; ti < total; ti++) {
        if (ti + 2 < total) {
            issue(ti + 2);
            asm volatile("cp.async.wait_group 2;");
        } else if (ti + 1 < total) {
            asm volatile("cp.async.wait_group 1;");
        } else {
            asm volatile("cp.async.wait_group 0;");
        }
        __syncthreads();

        const uint32_t so = (uint32_t)((ti % NSTAGE) * STAGE_BYTES);

        load_frags(so, 0, afr[0], bfr[0]);
#pragma unroll
        for (int ks = 0; ks < 4; ks++) {
            const int cur = ks & 1;
            const int nxt = cur ^ 1;
            if (ks < 3) load_frags(so, (ks + 1) * 16, afr[nxt], bfr[nxt]);
#pragma unroll
            for (int i = 0; i < 4; i++)
#pragma unroll
                for (int j = 0; j < 4; j++) {
                    uint32_t b0 = bfr[cur][j >> 1][(j & 1) * 2];
                    uint32_t b1 = bfr[cur][j >> 1][(j & 1) * 2 + 1];
                    asm volatile(
                        "mma.sync.aligned.m16n8k16.row.col.f32.bf16.bf16.f32 "
                        "{%0,%1,%2,%3}, {%4,%5,%6,%7}, {%8,%9}, {%0,%1,%2,%3};\n"
                        : "+f"(acc[i][j][0]), "+f"(acc[i][j][1]),
                          "+f"(acc[i][j][2]), "+f"(acc[i][j][3])
                        : "r"(afr[cur][i][0]), "r"(afr[cur][i][1]),
                          "r"(afr[cur][i][2]), "r"(afr[cur][i][3]),
                          "r"(b0), "r"(b1));
                }
        }
        __syncthreads();
    }

    // ---- staged epilogue: coalesced global stores ----
    __syncthreads();
    if (OUTBF16) {
        __nv_bfloat16* cs = (__nv_bfloat16*)smem_raw;   // [128][136]
        __nv_bfloat16* Cb = (__nv_bfloat16*)p.C;
#pragma unroll
        for (int i = 0; i < 4; i++) {
            int r0l = wm * 64 + i * 16 + g;
#pragma unroll
            for (int j = 0; j < 4; j++) {
                int cl = wn * 32 + j * 8 + tq * 2;
                float bv0 = p.bias[col0 + cl];
                float bv1 = p.bias[col0 + cl + 1];
                float x0 = acc[i][j][0] + bv0, x1 = acc[i][j][1] + bv1;
                float y0 = acc[i][j][2] + bv0, y1 = acc[i][j][3] + bv1;
                if (RELU) {
                    x0 = fmaxf(x0, 0.f); x1 = fmaxf(x1, 0.f);
                    y0 = fmaxf(y0, 0.f); y1 = fmaxf(y1, 0.f);
                }
                *(__nv_bfloat162*)&cs[r0l * 136 + cl]       = __floats2bfloat162_rn(x0, x1);
                *(__nv_bfloat162*)&cs[(r0l + 8) * 136 + cl] = __floats2bfloat162_rn(y0, y1);
            }
        }
        __syncthreads();
#pragma unroll
        for (int it = 0; it < 8; it++) {
            int idx = t + it * 256;
            int r   = idx >> 4;
            int c8  = (idx & 15) * 8;
            int gr  = row0 + r;
            int gc  = col0 + c8;
            if (gr < M) {
                if (gc + 8 <= N) {
                    *(uint4*)&Cb[(size_t)gr * N + gc] = *(uint4*)&cs[r * 136 + c8];
                } else {
                    for (int e = 0; e < 8; e++)
                        if (gc + e < N) Cb[(size_t)gr * N + gc + e] = cs[r * 136 + c8 + e];
                }
            }
        }
    } else {
        float* cs = (float*)smem_raw;   // [64][132] per half
        float* Cf = (float*)p.C;
#pragma unroll
        for (int half = 0; half < 2; half++) {
            __syncthreads();
            if (wm == half) {
#pragma unroll
                for (int i = 0; i < 4; i++) {
                    int r0l = i * 16 + g;
#pragma unroll
                    for (int j = 0; j < 4; j++) {
                        int cl = wn * 32 + j * 8 + tq * 2;
                        float bv0 = p.bias[col0 + cl];
                        float bv1 = p.bias[col0 + cl + 1];
                        cs[r0l * 132 + cl]           = acc[i][j][0] + bv0;
                        cs[r0l * 132 + cl + 1]       = acc[i][j][1] + bv1;
                        cs[(r0l + 8) * 132 + cl]     = acc[i][j][2] + bv0;
                        cs[(r0l + 8) * 132 + cl + 1] = acc[i][j][3] + bv1;
                    }
                }
            }
            __syncthreads();
#pragma unroll
            for (int it = 0; it < 32; it++) {
                int idx = t + it * 256;
                int r   = idx >> 7;
                int c   = idx & 127;
                int gr  = row0 + half * 64 + r;
                int gc  = col0 + c;
                if (gr < M && gc < N)
                    Cf[(size_t)gr * N + gc] = cs[r * 132 + c];
            }
        }
    }
}

template<bool RELU, bool OUTBF16>
__global__ __launch_bounds__(256, 2)
void gemm_fused_kernel(GemmParams p) {
    gemm_body<RELU, OUTBF16>(p, blockIdx.y);
}

// dual-problem launch: uniform branch, params referenced directly (no select)
__global__ __launch_bounds__(256, 2)
void gemm_dual_kernel(GemmParams p, GemmParams q, int tiles_p) {
    if ((int)blockIdx.y < tiles_p) {
        gemm_body<true, true>(p, blockIdx.y);
    } else {
        gemm_body<true, true>(q, blockIdx.y - tiles_p);
    }
}

// ---------------------------------------------------------------------------
__inline__ __device__ float warpMax(float v) {
#pragma unroll
    for (int o = 16; o; o >>= 1) v = fmaxf(v, __shfl_xor_sync(0xFFFFFFFFu, v, o));
    return v;
}
__inline__ __device__ float warpSum(float v) {
#pragma unroll
    for (int o = 16; o; o >>= 1) v += __shfl_xor_sync(0xFFFFFFFFu, v, o);
    return v;
}

__global__ void log_softmax_kernel(float* __restrict__ x, int N) {
    float* r = x + (size_t)blockIdx.x * N;
    int t = threadIdx.x;

    float m = -1e30f;
    for (int i = t; i < N; i += 128) m = fmaxf(m, r[i]);
    m = warpMax(m);
    __shared__ float shm[4];
    if ((t & 31) == 0) shm[t >> 5] = m;
    __syncthreads();
    m = fmaxf(fmaxf(shm[0], shm[1]), fmaxf(shm[2], shm[3]));

    float s = 0.f;
    for (int i = t; i < N; i += 128) s += expf(r[i] - m);
    s = warpSum(s);
    __shared__ float shs[4];
    if ((t & 31) == 0) shs[t >> 5] = s;
    __syncthreads();
    s = shs[0] + shs[1] + shs[2] + shs[3];

    float lse = m + logf(s);
    for (int i = t; i < N; i += 128) r[i] = r[i] - lse;
}

// ---------------------------------------------------------------------------
extern "C" void kernel_launch(void* const* d_in, const int* in_sizes, int n_in,
                              void* d_out, int out_size) {
    const float* x_paper          = (const float*)d_in[0];
    const float* emb_author       = (const float*)d_in[1];
    const float* lin_paper_w      = (const float*)d_in[2];
    const float* lin_paper_b      = (const float*)d_in[3];
    const float* c0_root_paper_w  = (const float*)d_in[4];
    const float* c0_root_paper_b  = (const float*)d_in[5];
    const float* c0_root_author_w = (const float*)d_in[6];
    const float* c0_root_author_b = (const float*)d_in[7];
    const float* c0_rel_writes_w  = (const float*)d_in[8];
    const float* c0_rel_cites_w   = (const float*)d_in[9];
    const float* c0_rel_revw_w    = (const float*)d_in[10];
    const float* c1_root_w        = (const float*)d_in[11];
    const float* c1_root_b        = (const float*)d_in[12];
    const float* c1_rel_writes_w  = (const float*)d_in[13];
    const float* c1_rel_cites_w   = (const float*)d_in[14];
    const int*   writes_src       = (const int*)d_in[15];
    const int*   writes_dst       = (const int*)d_in[16];
    const int*   cites_src        = (const int*)d_in[17];
    const int*   cites_dst        = (const int*)d_in[18];
    const int*   revw_src         = (const int*)d_in[19];
    const int*   revw_dst         = (const int*)d_in[20];

    const int E_W = in_sizes[15];
    const int E_C = in_sizes[17];
    float* out = (float*)d_out;

    __nv_bfloat16 *hp, *outp, *outa, *aggA, *aggB, *aggC, *emba, *xb;
    __nv_bfloat16 *wlin, *w0rp, *w0ra, *w0w, *w0c, *w0r, *w1rt, *w1w, *w1c;
    int *cntW, *cntC, *cntR, *rpW, *rpC, *rpR, *nxW, *nxC, *nxR, *csW, *csC, *csR, *bsum;
    cudaGetSymbolAddress((void**)&hp,   g_hp);
    cudaGetSymbolAddress((void**)&outp, g_outp);
    cudaGetSymbolAddress((void**)&outa, g_outa);
    cudaGetSymbolAddress((void**)&aggA, g_aggA);
    cudaGetSymbolAddress((void**)&aggB, g_aggB);
    cudaGetSymbolAddress((void**)&aggC, g_aggC);
    cudaGetSymbolAddress((void**)&emba, g_emba);
    cudaGetSymbolAddress((void**)&xb,   g_xb);
    cudaGetSymbolAddress((void**)&wlin, g_wlin);
    cudaGetSymbolAddress((void**)&w0rp, g_w0rp);
    cudaGetSymbolAddress((void**)&w0ra, g_w0ra);
    cudaGetSymbolAddress((void**)&w0w,  g_w0w);
    cudaGetSymbolAddress((void**)&w0c,  g_w0c);
    cudaGetSymbolAddress((void**)&w0r,  g_w0r);
    cudaGetSymbolAddress((void**)&w1rt, g_w1rt);
    cudaGetSymbolAddress((void**)&w1w,  g_w1w);
    cudaGetSymbolAddress((void**)&w1c,  g_w1c);
    cudaGetSymbolAddress((void**)&cntW, g_cntW);
    cudaGetSymbolAddress((void**)&cntC, g_cntC);
    cudaGetSymbolAddress((void**)&cntR, g_cntR);
    cudaGetSymbolAddress((void**)&rpW,  g_rpW);
    cudaGetSymbolAddress((void**)&rpC,  g_rpC);
    cudaGetSymbolAddress((void**)&rpR,  g_rpR);
    cudaGetSymbolAddress((void**)&nxW,  g_nxW);
    cudaGetSymbolAddress((void**)&nxC,  g_nxC);
    cudaGetSymbolAddress((void**)&nxR,  g_nxR);
    cudaGetSymbolAddress((void**)&csW,  g_csW);
    cudaGetSymbolAddress((void**)&csC,  g_csC);
    cudaGetSymbolAddress((void**)&csR,  g_csR);
    cudaGetSymbolAddress((void**)&bsum, g_bsum);

    cudaFuncSetAttribute(gemm_fused_kernel<false, true >, cudaFuncAttributeMaxDynamicSharedMemorySize, GEMM_SMEM);
    cudaFuncSetAttribute(gemm_fused_kernel<false, false>, cudaFuncAttributeMaxDynamicSharedMemorySize, GEMM_SMEM);
    cudaFuncSetAttribute(gemm_dual_kernel, cudaFuncAttributeMaxDynamicSharedMemorySize, GEMM_SMEM);

    const int tiles_P = (P_N + BM - 1) / BM;   // 782
    const int tiles_A = (A_N + BM - 1) / BM;   // 391

    // 0: both feature conversions
    {
        int n0 = A_N * H_C / 4, n1 = P_N * IN_C / 4;
        f2b_all_kernel<<<(n0 + n1 + 255) / 256, 256>>>(
            (const float4*)emb_author, (uint2*)emba, n0,
            (const float4*)x_paper, (uint2*)xb, n1);
    }

    // 1: all weight conversions
    {
        W2B b = {};
        const float* srcs[9] = {lin_paper_w, c0_root_paper_w, c0_root_author_w,
                                c0_rel_writes_w, c0_rel_cites_w, c0_rel_revw_w,
                                c1_root_w, c1_rel_writes_w, c1_rel_cites_w};
        __nv_bfloat16* dsts[9] = {wlin, w0rp, w0ra, w0w, w0c, w0r, w1rt, w1w, w1c};
        int Ns[9]    = {H_C, H_C, H_C, H_C, H_C, H_C, OUT_C, OUT_C, OUT_C};
        int Npads[9] = {H_C, H_C, H_C, H_C, H_C, H_C, 352, 352, 352};
        int Ks[9]    = {IN_C, H_C, H_C, H_C, H_C, H_C, H_C, H_C, H_C};
        int cum = 0;
        for (int q = 0; q < 9; q++) {
            b.src[q] = srcs[q]; b.dst[q] = dsts[q];
            b.N[q] = Ns[q]; b.Npad[q] = Npads[q];
            b.cum[q] = cum; cum += Ks[q] * Npads[q];
        }
        b.cum[9] = cum;
        w2b_all_kernel<<<(cum + 255) / 256, 256>>>(b);
    }

    // 2: zero count arrays
    {
        int na4 = P_N / 4, nb4 = P_N / 4, nc4 = A_N / 4;
        fill3_kernel<<<(na4 + nb4 + nc4 + 255) / 256, 256>>>(
            (int4*)cntW, na4, (int4*)cntC, nb4, (int4*)cntR, nc4);
    }

    // 3: GEMM1 (hp = x@Wlin + b) — stays in the ncu-captured slot
    {
        GemmParams p = {};
        p.A[0] = xb; p.B[0] = wlin; p.K[0] = IN_C;
        p.nseg = 1; p.bias = lin_paper_b; p.C = hp; p.M = P_N; p.N = H_C; p.Npad = H_C;
        dim3 grid(H_C / BN, tiles_P);
        gemm_fused_kernel<false, true><<<grid, 256, GEMM_SMEM>>>(p);
    }

    // 4: all degree counts
    count3_kernel<<<(E_W + E_C + E_W + 255) / 256, 256>>>(
        writes_dst, E_W, cntW, cites_dst, E_C, cntC, revw_dst, E_W, cntR);

    // 5-8: merged scans + CSR builds
    scan1_3_kernel<<<2 * NB_P + NB_A, SCB>>>(cntW, cntC, cntR, bsum);
    scan2_3_kernel<<<1, SCB>>>(bsum);
    scan3_3_kernel<<<2 * NB_P + NB_A, SCB>>>(cntW, cntC, cntR, bsum,
                                             rpW, rpC, rpR, nxW, nxC, nxR);
    build3_kernel<<<(E_W + E_C + E_W + 255) / 256, 256>>>(
        writes_src, writes_dst, E_W, nxW, csW,
        cites_src, cites_dst, E_C, nxC, csC,
        revw_src, revw_dst, E_W, nxR, csR);

    // 9: all three layer-0 gathers
    {
        GMulti g = {};
        g.j[0] = {emba, rpW, csW, aggA};
        g.j[1] = {hp,   rpC, csC, aggB};
        g.j[2] = {hp,   rpR, csR, aggC};
        g.cum[0] = 0; g.cum[1] = P_N; g.cum[2] = 2 * P_N; g.cum[3] = 2 * P_N + A_N;
        gather_multi_kernel<<<(g.cum[3] + 7) / 8, 256>>>(g);
    }

    // 10: layer-0 paper + author GEMMs (uniform-branch dual)
    {
        GemmParams p = {};
        p.A[0] = hp;   p.B[0] = w0rp; p.K[0] = H_C;
        p.A[1] = aggA; p.B[1] = w0w;  p.K[1] = H_C;
        p.A[2] = aggB; p.B[2] = w0c;  p.K[2] = H_C;
        p.nseg = 3; p.bias = c0_root_paper_b; p.C = outp; p.M = P_N; p.N = H_C; p.Npad = H_C;
        GemmParams q = {};
        q.A[0] = emba; q.B[0] = w0ra; q.K[0] = H_C;
        q.A[1] = aggC; q.B[1] = w0r;  q.K[1] = H_C;
        q.nseg = 2; q.bias = c0_root_author_b; q.C = outa; q.M = A_N; q.N = H_C; q.Npad = H_C;
        dim3 grid(H_C / BN, tiles_P + tiles_A);
        gemm_dual_kernel<<<grid, 256, GEMM_SMEM>>>(p, q, tiles_P);
    }

    // 11: both layer-1 gathers
    {
        GMulti g = {};
        g.j[0] = {outa, rpW, csW, aggA};
        g.j[1] = {outp, rpC, csC, aggB};
        g.j[2] = {outp, rpC, csC, aggB};   // unused (cum[2]==cum[3])
        g.cum[0] = 0; g.cum[1] = P_N; g.cum[2] = 2 * P_N; g.cum[3] = 2 * P_N;
        gather_multi_kernel<<<(g.cum[3] + 7) / 8, 256>>>(g);
    }

    // 12: final GEMM (fp32 out)
    {
        GemmParams p = {};
        p.A[0] = outp; p.B[0] = w1rt; p.K[0] = H_C;
        p.A[1] = aggA; p.B[1] = w1w;  p.K[1] = H_C;
        p.A[2] = aggB; p.B[2] = w1c;  p.K[2] = H_C;
        p.nseg = 3; p.bias = c1_root_b; p.C = out; p.M = P_N; p.N = OUT_C; p.Npad = 352;
        dim3 grid((OUT_C + BN - 1) / BN, tiles_P);
        gemm_fused_kernel<false, false><<<grid, 256, GEMM_SMEM>>>(p);
    }

    // 13: log_softmax
    log_softmax_kernel<<<P_N, 128>>>(out, OUT_C);
}

// round 14
// speedup vs baseline: 1.1496x; 1.1496x over previous
#include <cuda_runtime.h>
#include <cuda_bf16.h>
#include <cstdint>

// ---------------------------------------------------------------------------
// RGCN forward. CSR gather-mean (warp-per-row, bf16), pipelined bf16 HMMA
// GEMMs: BK=64, 3-stage cp.async, ldmatrix + register fragment double-buffer,
// staged epilogues. Separate GEMM/gather launches (dual-kernel merge reverted).
// P=100000, A=50000, IN=128, H=256, OUT=349
// ---------------------------------------------------------------------------

#define P_N   100000
#define A_N   50000
#define IN_C  128
#define H_C   256
#define OUT_C 349
#define EW_MAX 600000
#define EC_MAX 1000000
#define NB_P  98
#define NB_A  49

// bf16 feature buffers
__device__ __nv_bfloat16 g_hp  [(size_t)P_N * H_C];
__device__ __nv_bfloat16 g_outp[(size_t)P_N * H_C];
__device__ __nv_bfloat16 g_outa[(size_t)A_N * H_C];
__device__ __nv_bfloat16 g_aggA[(size_t)P_N * H_C];
__device__ __nv_bfloat16 g_aggB[(size_t)P_N * H_C];
__device__ __nv_bfloat16 g_aggC[(size_t)A_N * H_C];
__device__ __nv_bfloat16 g_emba[(size_t)A_N * H_C];
__device__ __nv_bfloat16 g_xb  [(size_t)P_N * IN_C];

// bf16 weights (padded to Npad columns)
__device__ __nv_bfloat16 g_wlin [IN_C * H_C];
__device__ __nv_bfloat16 g_w0rp [H_C * H_C];
__device__ __nv_bfloat16 g_w0ra [H_C * H_C];
__device__ __nv_bfloat16 g_w0w  [H_C * H_C];
__device__ __nv_bfloat16 g_w0c  [H_C * H_C];
__device__ __nv_bfloat16 g_w0r  [H_C * H_C];
__device__ __nv_bfloat16 g_w1rt [H_C * 352];
__device__ __nv_bfloat16 g_w1w  [H_C * 352];
__device__ __nv_bfloat16 g_w1c  [H_C * 352];

// CSR scratch
__device__ int g_cntW[P_N], g_cntC[P_N], g_cntR[A_N];
__device__ int g_rpW[P_N + 1], g_rpC[P_N + 1], g_rpR[A_N + 1];
__device__ int g_nxW[P_N], g_nxC[P_N], g_nxR[A_N];
__device__ int g_csW[EW_MAX], g_csC[EC_MAX], g_csR[EW_MAX];
__device__ int g_bsum[256];

// ---------------------------------------------------------------------------
__global__ void fill3_kernel(int4* a, int na4, int4* b, int nb4, int4* c, int nc4) {
    int i = blockIdx.x * blockDim.x + threadIdx.x;
    int4 z = make_int4(0, 0, 0, 0);
    if (i < na4) a[i] = z;
    else if (i < na4 + nb4) b[i - na4] = z;
    else if (i < na4 + nb4 + nc4) c[i - na4 - nb4] = z;
}

__global__ void count3_kernel(const int* __restrict__ wdst, int EW, int* __restrict__ cntW,
                              const int* __restrict__ cdst, int EC, int* __restrict__ cntC,
                              const int* __restrict__ rdst, int ER, int* __restrict__ cntR) {
    int i = blockIdx.x * blockDim.x + threadIdx.x;
    if (i < EW) atomicAdd(&cntW[wdst[i]], 1);
    else if (i < EW + EC) atomicAdd(&cntC[cdst[i - EW]], 1);
    else if (i < EW + EC + ER) atomicAdd(&cntR[rdst[i - EW - EC]], 1);
}

// ---------------------------------------------------------------------------
#define SCB 1024

__global__ void scan1_3_kernel(const int* __restrict__ cW, const int* __restrict__ cC,
                               const int* __restrict__ cR, int* __restrict__ bsum) {
    int b = blockIdx.x;
    const int* cnt; int n, base, lb;
    if (b < NB_P)           { cnt = cW; n = P_N; base = 0;        lb = b; }
    else if (b < 2 * NB_P)  { cnt = cC; n = P_N; base = NB_P;     lb = b - NB_P; }
    else                    { cnt = cR; n = A_N; base = 2 * NB_P; lb = b - 2 * NB_P; }
    __shared__ int sh[SCB];
    int tid = threadIdx.x;
    int i = lb * SCB + tid;
    sh[tid] = (i < n) ? cnt[i] : 0;
    __syncthreads();
    for (int off = SCB / 2; off; off >>= 1) {
        if (tid < off) sh[tid] += sh[tid + off];
        __syncthreads();
    }
    if (!tid) bsum[base + lb] = sh[0];
}

__global__ void scan2_3_kernel(int* __restrict__ bsum) {
    __shared__ int sh[SCB];
    int tid = threadIdx.x;
    int bases[3] = {0, NB_P, 2 * NB_P};
    int nbs[3]   = {NB_P, NB_P, NB_A};
#pragma unroll
    for (int r = 0; r < 3; r++) {
        int nb = nbs[r];
        int v = (tid < nb) ? bsum[bases[r] + tid] : 0;
        sh[tid] = v;
        __syncthreads();
        for (int off = 1; off < SCB; off <<= 1) {
            int a = (tid >= off) ? sh[tid - off] : 0;
            __syncthreads();
            sh[tid] += a;
            __syncthreads();
        }
        if (tid < nb) bsum[bases[r] + tid] = sh[tid] - v;
        __syncthreads();
    }
}

__global__ void scan3_3_kernel(const int* __restrict__ cW, const int* __restrict__ cC,
                               const int* __restrict__ cR, const int* __restrict__ bsum,
                               int* __restrict__ rpW, int* __restrict__ rpC, int* __restrict__ rpR,
                               int* __restrict__ nxW, int* __restrict__ nxC, int* __restrict__ nxR) {
    int b = blockIdx.x;
    const int* cnt; int n, base, lb; int *rowptr, *nextp;
    if (b < NB_P)          { cnt = cW; n = P_N; base = 0;        lb = b;            rowptr = rpW; nextp = nxW; }
    else if (b < 2 * NB_P) { cnt = cC; n = P_N; base = NB_P;     lb = b - NB_P;     rowptr = rpC; nextp = nxC; }
    else                   { cnt = cR; n = A_N; base = 2 * NB_P; lb = b - 2 * NB_P; rowptr = rpR; nextp = nxR; }
    __shared__ int sh[SCB];
    int tid = threadIdx.x;
    int i = lb * SCB + tid;
    int v = (i < n) ? cnt[i] : 0;
    sh[tid] = v;
    __syncthreads();
    for (int off = 1; off < SCB; off <<= 1) {
        int a = (tid >= off) ? sh[tid - off] : 0;
        __syncthreads();
        sh[tid] += a;
        __syncthreads();
    }
    int excl = sh[tid] - v + bsum[base + lb];
    if (i < n) { rowptr[i] = excl; nextp[i] = excl; }
    if (i == n - 1) rowptr[n] = excl + v;
}

__global__ void build3_kernel(const int* __restrict__ wsrc, const int* __restrict__ wdst, int EW,
                              int* __restrict__ nxW, int* __restrict__ csW,
                              const int* __restrict__ csrc, const int* __restrict__ cdst, int EC,
                              int* __restrict__ nxC, int* __restrict__ csC,
                              const int* __restrict__ rsrc, const int* __restrict__ rdst, int ER,
                              int* __restrict__ nxR, int* __restrict__ csR) {
    int i = blockIdx.x * blockDim.x + threadIdx.x;
    if (i < EW) {
        int p = atomicAdd(&nxW[wdst[i]], 1); csW[p] = wsrc[i];
    } else if (i < EW + EC) {
        int k = i - EW;
        int p = atomicAdd(&nxC[cdst[k]], 1); csC[p] = csrc[k];
    } else if (i < EW + EC + ER) {
        int k = i - EW - EC;
        int p = atomicAdd(&nxR[rdst[k]], 1); csR[p] = rsrc[k];
    }
}

// ---------------------------------------------------------------------------
__global__ void f2b_all_kernel(const float4* __restrict__ in0, uint2* __restrict__ out0, int n0,
                               const float4* __restrict__ in1, uint2* __restrict__ out1, int n1) {
    int i = blockIdx.x * blockDim.x + threadIdx.x;
    const float4* in; uint2* out; int k;
    if (i < n0)           { in = in0; out = out0; k = i; }
    else if (i < n0 + n1) { in = in1; out = out1; k = i - n0; }
    else return;
    float4 v = in[k];
    __nv_bfloat162 a = __floats2bfloat162_rn(v.x, v.y);
    __nv_bfloat162 b = __floats2bfloat162_rn(v.z, v.w);
    uint2 o;
    o.x = *(uint32_t*)&a;
    o.y = *(uint32_t*)&b;
    out[k] = o;
}

struct W2B {
    const float* src[9];
    __nv_bfloat16* dst[9];
    int N[9];
    int Npad[9];
    int cum[10];
};
__global__ void w2b_all_kernel(W2B b) {
    int i = blockIdx.x * blockDim.x + threadIdx.x;
    if (i >= b.cum[9]) return;
    int r = 0;
#pragma unroll
    for (int q = 0; q < 8; q++) if (i >= b.cum[q + 1]) r = q + 1;
    int local = i - b.cum[r];
    int Npad = b.Npad[r], N = b.N[r];
    int k = local / Npad, c = local - k * Npad;
    b.dst[r][local] = __float2bfloat16(c < N ? b.src[r][k * N + c] : 0.f);
}

// ---------------------------------------------------------------------------
// Gather-mean (bf16 in/out, fp32 accumulation). One warp per dst row;
// each lane owns 8 channels (one uint4 = 16B per neighbor).
// ---------------------------------------------------------------------------
__device__ __forceinline__ void acc8(float* s, uint4 u) {
    float2 f0 = __bfloat1622float2(*(__nv_bfloat162*)&u.x);
    float2 f1 = __bfloat1622float2(*(__nv_bfloat162*)&u.y);
    float2 f2 = __bfloat1622float2(*(__nv_bfloat162*)&u.z);
    float2 f3 = __bfloat1622float2(*(__nv_bfloat162*)&u.w);
    s[0] += f0.x; s[1] += f0.y; s[2] += f1.x; s[3] += f1.y;
    s[4] += f2.x; s[5] += f2.y; s[6] += f3.x; s[7] += f3.y;
}

__global__ void gather_mean_kernel(const __nv_bfloat16* __restrict__ feat,
                                   const int* __restrict__ rowptr,
                                   const int* __restrict__ csr_src,
                                   int num_dst,
                                   __nv_bfloat16* __restrict__ agg) {
    int group = blockIdx.x * 8 + (threadIdx.x >> 5);
    int lane  = threadIdx.x & 31;
    if (group >= num_dst) return;
    int beg = rowptr[group], end = rowptr[group + 1];
    int c8 = lane * 8;

    float s[8] = {0.f, 0.f, 0.f, 0.f, 0.f, 0.f, 0.f, 0.f};
    int i = beg;
    for (; i + 1 < end; i += 2) {
        int sa = csr_src[i];
        int sb = csr_src[i + 1];
        uint4 ua = *(const uint4*)&feat[(size_t)sa * H_C + c8];
        uint4 ub = *(const uint4*)&feat[(size_t)sb * H_C + c8];
        acc8(s, ua);
        acc8(s, ub);
    }
    if (i < end) {
        uint4 ua = *(const uint4*)&feat[(size_t)csr_src[i] * H_C + c8];
        acc8(s, ua);
    }
    float inv = (end > beg) ? 1.0f / (float)(end - beg) : 0.f;
    __nv_bfloat162 o0 = __floats2bfloat162_rn(s[0] * inv, s[1] * inv);
    __nv_bfloat162 o1 = __floats2bfloat162_rn(s[2] * inv, s[3] * inv);
    __nv_bfloat162 o2 = __floats2bfloat162_rn(s[4] * inv, s[5] * inv);
    __nv_bfloat162 o3 = __floats2bfloat162_rn(s[6] * inv, s[7] * inv);
    uint4 o;
    o.x = *(uint32_t*)&o0; o.y = *(uint32_t*)&o1;
    o.z = *(uint32_t*)&o2; o.w = *(uint32_t*)&o3;
    *(uint4*)&agg[(size_t)group * H_C + c8] = o;
}

// ---------------------------------------------------------------------------
// Pipelined fused multi-segment bf16 GEMM, BK=64, 3-stage cp.async,
// register fragment double-buffer, staged epilogue.
// ---------------------------------------------------------------------------
#define BM 128
#define BN 128
#define BK 64
#define PK 72
#define PN 136
#define A_BYTES (BM * PK * 2)
#define B_BYTES (BK * PN * 2)
#define STAGE_BYTES (A_BYTES + B_BYTES)     // 35840
#define NSTAGE 3
#define GEMM_SMEM (NSTAGE * STAGE_BYTES)    // 107520

struct GemmParams {
    const __nv_bfloat16* A[3];
    const __nv_bfloat16* B[3];
    int          K[3];
    int          nseg;
    const float* bias;
    void*        C;
    int          M, N, Npad;
};

__device__ __forceinline__ void cp16(uint32_t dst, const void* src, bool pred) {
    int sz = pred ? 16 : 0;
    asm volatile("cp.async.cg.shared.global [%0], [%1], 16, %2;"
                 :: "r"(dst), "l"(src), "r"(sz));
}

template<bool RELU, bool OUTBF16>
__device__ __forceinline__ void gemm_body(const GemmParams& p, int by) {
    extern __shared__ __align__(16) unsigned char smem_raw[];

    const int t    = threadIdx.x;
    const int lane = t & 31;
    const int w    = t >> 5;
    const int wm   = w & 1;
    const int wn   = w >> 1;
    const int g    = lane >> 2;
    const int tq   = lane & 3;
    const int row0 = by * BM;
    const int col0 = blockIdx.x * BN;
    const int M = p.M, N = p.N, Npad = p.Npad;
    const int nseg = p.nseg;

    const int kt0 = p.K[0] >> 6;
    const int kt1 = (nseg > 1) ? (p.K[1] >> 6) : 0;
    const int kt2 = (nseg > 2) ? (p.K[2] >> 6) : 0;
    const int total = kt0 + kt1 + kt2;

    const uint32_t smBase = (uint32_t)__cvta_generic_to_shared(smem_raw);

    const uint32_t aBase = smBase +
        (uint32_t)(((wm * 64 + (lane & 15)) * PK + ((lane >> 4) << 3)) << 1);
    const uint32_t bBase = smBase + A_BYTES +
        (uint32_t)(((lane & 15) * PN + wn * 32 + ((lane >> 4) << 3)) << 1);

    float acc[4][4][4];
#pragma unroll
    for (int i = 0; i < 4; i++)
#pragma unroll
        for (int j = 0; j < 4; j++)
#pragma unroll
            for (int v = 0; v < 4; v++) acc[i][j][v] = 0.f;

    auto issue = [&](int ti) {
        int s = 0, rem = ti;
        if (rem >= kt0)           { rem -= kt0; s = 1; }
        if (s == 1 && rem >= kt1) { rem -= kt1; s = 2; }
        int k0 = rem * BK;
        const __nv_bfloat16* A = p.A[s];
        const __nv_bfloat16* B = p.B[s];
        int K = p.K[s];
        uint32_t sb = smBase + (uint32_t)((ti % NSTAGE) * STAGE_BYTES);
#pragma unroll
        for (int it = 0; it < 4; it++) {
            int idx = t + it * 256;
            int r   = idx >> 3;
            int c8  = (idx & 7) * 8;
            int gr  = row0 + r;
            bool ok = (gr < M);
            int  sr = ok ? gr : 0;
            uint32_t dst = sb + (uint32_t)((r * PK + c8) << 1);
            cp16(dst, A + (size_t)sr * K + k0 + c8, ok);
        }
#pragma unroll
        for (int it = 0; it < 4; it++) {
            int idx = t + it * 256;
            int kr  = idx >> 4;
            int c8  = (idx & 15) * 8;
            int gc  = col0 + c8;
            bool ok = (gc < Npad);
            int  sc = ok ? gc : 0;
            uint32_t dst = sb + A_BYTES + (uint32_t)((kr * PN + c8) << 1);
            cp16(dst, B + (size_t)(k0 + kr) * Npad + sc, ok);
        }
        asm volatile("cp.async.commit_group;");
    };

    auto load_frags = [&](uint32_t so, int ko, uint32_t (*af)[4], uint32_t (*bf)[4]) {
#pragma unroll
        for (int i = 0; i < 4; i++) {
            uint32_t addr = aBase + so + (uint32_t)(((i * 16) * PK + ko) << 1);
            asm volatile("ldmatrix.sync.aligned.m8n8.x4.shared.b16 {%0,%1,%2,%3}, [%4];"
                         : "=r"(af[i][0]), "=r"(af[i][1]), "=r"(af[i][2]), "=r"(af[i][3])
                         : "r"(addr));
        }
#pragma unroll
        for (int jj = 0; jj < 2; jj++) {
            uint32_t addr = bBase + so + (uint32_t)((ko * PN + jj * 16) << 1);
            asm volatile("ldmatrix.sync.aligned.m8n8.x4.trans.shared.b16 {%0,%1,%2,%3}, [%4];"
                         : "=r"(bf[jj][0]), "=r"(bf[jj][1]), "=r"(bf[jj][2]), "=r"(bf[jj][3])
                         : "r"(addr));
        }
    };

    issue(0);
    if (total > 1) issue(1);

    uint32_t afr[2][4][4];
    uint32_t bfr[2][2][4];

    for (int ti = 0; ti < total; ti++) {
        if (ti + 2 < total) {
            issue(ti + 2);
            asm volatile("cp.async.wait_group 2;");
        } else if (ti + 1 < total) {
            asm volatile("cp.async.wait_group 1;");
        } else {
            asm volatile("cp.async.wait_group 0;");
        }
        __syncthreads();

        const uint32_t so = (uint32_t)((ti % NSTAGE) * STAGE_BYTES);

        load_frags(so, 0, afr[0], bfr[0]);
#pragma unroll
        for (int ks = 0; ks < 4; ks++) {
            const int cur = ks & 1;
            const int nxt = cur ^ 1;
            if (ks < 3) load_frags(so, (ks + 1) * 16, afr[nxt], bfr[nxt]);
#pragma unroll
            for (int i = 0; i < 4; i++)
#pragma unroll
                for (int j = 0; j < 4; j++) {
                    uint32_t b0 = bfr[cur][j >> 1][(j & 1) * 2];
                    uint32_t b1 = bfr[cur][j >> 1][(j & 1) * 2 + 1];
                    asm volatile(
                        "mma.sync.aligned.m16n8k16.row.col.f32.bf16.bf16.f32 "
                        "{%0,%1,%2,%3}, {%4,%5,%6,%7}, {%8,%9}, {%0,%1,%2,%3};\n"
                        : "+f"(acc[i][j][0]), "+f"(acc[i][j][1]),
                          "+f"(acc[i][j][2]), "+f"(acc[i][j][3])
                        : "r"(afr[cur][i][0]), "r"(afr[cur][i][1]),
                          "r"(afr[cur][i][2]), "r"(afr[cur][i][3]),
                          "r"(b0), "r"(b1));
                }
        }
        __syncthreads();
    }

    // ---- staged epilogue: coalesced global stores ----
    __syncthreads();
    if (OUTBF16) {
        __nv_bfloat16* cs = (__nv_bfloat16*)smem_raw;   // [128][136]
        __nv_bfloat16* Cb = (__nv_bfloat16*)p.C;
#pragma unroll
        for (int i = 0; i < 4; i++) {
            int r0l = wm * 64 + i * 16 + g;
#pragma unroll
            for (int j = 0; j < 4; j++) {
                int cl = wn * 32 + j * 8 + tq * 2;
                float bv0 = p.bias[col0 + cl];
                float bv1 = p.bias[col0 + cl + 1];
                float x0 = acc[i][j][0] + bv0, x1 = acc[i][j][1] + bv1;
                float y0 = acc[i][j][2] + bv0, y1 = acc[i][j][3] + bv1;
                if (RELU) {
                    x0 = fmaxf(x0, 0.f); x1 = fmaxf(x1, 0.f);
                    y0 = fmaxf(y0, 0.f); y1 = fmaxf(y1, 0.f);
                }
                *(__nv_bfloat162*)&cs[r0l * 136 + cl]       = __floats2bfloat162_rn(x0, x1);
                *(__nv_bfloat162*)&cs[(r0l + 8) * 136 + cl] = __floats2bfloat162_rn(y0, y1);
            }
        }
        __syncthreads();
#pragma unroll
        for (int it = 0; it < 8; it++) {
            int idx = t + it * 256;
            int r   = idx >> 4;
            int c8  = (idx & 15) * 8;
            int gr  = row0 + r;
            int gc  = col0 + c8;
            if (gr < M) {
                if (gc + 8 <= N) {
                    *(uint4*)&Cb[(size_t)gr * N + gc] = *(uint4*)&cs[r * 136 + c8];
                } else {
                    for (int e = 0; e < 8; e++)
                        if (gc + e < N) Cb[(size_t)gr * N + gc + e] = cs[r * 136 + c8 + e];
                }
            }
        }
    } else {
        float* cs = (float*)smem_raw;   // [64][132] per half
        float* Cf = (float*)p.C;
#pragma unroll
        for (int half = 0; half < 2; half++) {
            __syncthreads();
            if (wm == half) {
#pragma unroll
                for (int i = 0; i < 4; i++) {
                    int r0l = i * 16 + g;
#pragma unroll
                    for (int j = 0; j < 4; j++) {
                        int cl = wn * 32 + j * 8 + tq * 2;
                        float bv0 = p.bias[col0 + cl];
                        float bv1 = p.bias[col0 + cl + 1];
                        cs[r0l * 132 + cl]           = acc[i][j][0] + bv0;
                        cs[r0l * 132 + cl + 1]       = acc[i][j][1] + bv1;
                        cs[(r0l + 8) * 132 + cl]     = acc[i][j][2] + bv0;
                        cs[(r0l + 8) * 132 + cl + 1] = acc[i][j][3] + bv1;
                    }
                }
            }
            __syncthreads();
#pragma unroll
            for (int it = 0; it < 32; it++) {
                int idx = t + it * 256;
                int r   = idx >> 7;
                int c   = idx & 127;
                int gr  = row0 + half * 64 + r;
                int gc  = col0 + c;
                if (gr < M && gc < N)
                    Cf[(size_t)gr * N + gc] = cs[r * 132 + c];
            }
        }
    }
}

template<bool RELU, bool OUTBF16>
__global__ __launch_bounds__(256, 2)
void gemm_fused_kernel(GemmParams p) {
    gemm_body<RELU, OUTBF16>(p, blockIdx.y);
}

// ---------------------------------------------------------------------------
__inline__ __device__ float warpMax(float v) {
#pragma unroll
    for (int o = 16; o; o >>= 1) v = fmaxf(v, __shfl_xor_sync(0xFFFFFFFFu, v, o));
    return v;
}
__inline__ __device__ float warpSum(float v) {
#pragma unroll
    for (int o = 16; o; o >>= 1) v += __shfl_xor_sync(0xFFFFFFFFu, v, o);
    return v;
}

__global__ void log_softmax_kernel(float* __restrict__ x, int N) {
    float* r = x + (size_t)blockIdx.x * N;
    int t = threadIdx.x;

    float m = -1e30f;
    for (int i = t; i < N; i += 128) m = fmaxf(m, r[i]);
    m = warpMax(m);
    __shared__ float shm[4];
    if ((t & 31) == 0) shm[t >> 5] = m;
    __syncthreads();
    m = fmaxf(fmaxf(shm[0], shm[1]), fmaxf(shm[2], shm[3]));

    float s = 0.f;
    for (int i = t; i < N; i += 128) s += expf(r[i] - m);
    s = warpSum(s);
    __shared__ float shs[4];
    if ((t & 31) == 0) shs[t >> 5] = s;
    __syncthreads();
    s = shs[0] + shs[1] + shs[2] + shs[3];

    float lse = m + logf(s);
    for (int i = t; i < N; i += 128) r[i] = r[i] - lse;
}

// ---------------------------------------------------------------------------
static void run_gather(const __nv_bfloat16* feat, const int* rowptr, const int* csr_src,
                       int num_dst, __nv_bfloat16* agg) {
    gather_mean_kernel<<<(num_dst + 7) / 8, 256>>>(feat, rowptr, csr_src, num_dst, agg);
}

extern "C" void kernel_launch(void* const* d_in, const int* in_sizes, int n_in,
                              void* d_out, int out_size) {
    const float* x_paper          = (const float*)d_in[0];
    const float* emb_author       = (const float*)d_in[1];
    const float* lin_paper_w      = (const float*)d_in[2];
    const float* lin_paper_b      = (const float*)d_in[3];
    const float* c0_root_paper_w  = (const float*)d_in[4];
    const float* c0_root_paper_b  = (const float*)d_in[5];
    const float* c0_root_author_w = (const float*)d_in[6];
    const float* c0_root_author_b = (const float*)d_in[7];
    const float* c0_rel_writes_w  = (const float*)d_in[8];
    const float* c0_rel_cites_w   = (const float*)d_in[9];
    const float* c0_rel_revw_w    = (const float*)d_in[10];
    const float* c1_root_w        = (const float*)d_in[11];
    const float* c1_root_b        = (const float*)d_in[12];
    const float* c1_rel_writes_w  = (const float*)d_in[13];
    const float* c1_rel_cites_w   = (const float*)d_in[14];
    const int*   writes_src       = (const int*)d_in[15];
    const int*   writes_dst       = (const int*)d_in[16];
    const int*   cites_src        = (const int*)d_in[17];
    const int*   cites_dst        = (const int*)d_in[18];
    const int*   revw_src         = (const int*)d_in[19];
    const int*   revw_dst         = (const int*)d_in[20];

    const int E_W = in_sizes[15];
    const int E_C = in_sizes[17];
    float* out = (float*)d_out;

    __nv_bfloat16 *hp, *outp, *outa, *aggA, *aggB, *aggC, *emba, *xb;
    __nv_bfloat16 *wlin, *w0rp, *w0ra, *w0w, *w0c, *w0r, *w1rt, *w1w, *w1c;
    int *cntW, *cntC, *cntR, *rpW, *rpC, *rpR, *nxW, *nxC, *nxR, *csW, *csC, *csR, *bsum;
    cudaGetSymbolAddress((void**)&hp,   g_hp);
    cudaGetSymbolAddress((void**)&outp, g_outp);
    cudaGetSymbolAddress((void**)&outa, g_outa);
    cudaGetSymbolAddress((void**)&aggA, g_aggA);
    cudaGetSymbolAddress((void**)&aggB, g_aggB);
    cudaGetSymbolAddress((void**)&aggC, g_aggC);
    cudaGetSymbolAddress((void**)&emba, g_emba);
    cudaGetSymbolAddress((void**)&xb,   g_xb);
    cudaGetSymbolAddress((void**)&wlin, g_wlin);
    cudaGetSymbolAddress((void**)&w0rp, g_w0rp);
    cudaGetSymbolAddress((void**)&w0ra, g_w0ra);
    cudaGetSymbolAddress((void**)&w0w,  g_w0w);
    cudaGetSymbolAddress((void**)&w0c,  g_w0c);
    cudaGetSymbolAddress((void**)&w0r,  g_w0r);
    cudaGetSymbolAddress((void**)&w1rt, g_w1rt);
    cudaGetSymbolAddress((void**)&w1w,  g_w1w);
    cudaGetSymbolAddress((void**)&w1c,  g_w1c);
    cudaGetSymbolAddress((void**)&cntW, g_cntW);
    cudaGetSymbolAddress((void**)&cntC, g_cntC);
    cudaGetSymbolAddress((void**)&cntR, g_cntR);
    cudaGetSymbolAddress((void**)&rpW,  g_rpW);
    cudaGetSymbolAddress((void**)&rpC,  g_rpC);
    cudaGetSymbolAddress((void**)&rpR,  g_rpR);
    cudaGetSymbolAddress((void**)&nxW,  g_nxW);
    cudaGetSymbolAddress((void**)&nxC,  g_nxC);
    cudaGetSymbolAddress((void**)&nxR,  g_nxR);
    cudaGetSymbolAddress((void**)&csW,  g_csW);
    cudaGetSymbolAddress((void**)&csC,  g_csC);
    cudaGetSymbolAddress((void**)&csR,  g_csR);
    cudaGetSymbolAddress((void**)&bsum, g_bsum);

    cudaFuncSetAttribute(gemm_fused_kernel<false, true >, cudaFuncAttributeMaxDynamicSharedMemorySize, GEMM_SMEM);
    cudaFuncSetAttribute(gemm_fused_kernel<true,  true >, cudaFuncAttributeMaxDynamicSharedMemorySize, GEMM_SMEM);
    cudaFuncSetAttribute(gemm_fused_kernel<false, false>, cudaFuncAttributeMaxDynamicSharedMemorySize, GEMM_SMEM);

    const int tiles_P = (P_N + BM - 1) / BM;   // 782
    const int tiles_A = (A_N + BM - 1) / BM;   // 391

    // 0: both feature conversions
    {
        int n0 = A_N * H_C / 4, n1 = P_N * IN_C / 4;
        f2b_all_kernel<<<(n0 + n1 + 255) / 256, 256>>>(
            (const float4*)emb_author, (uint2*)emba, n0,
            (const float4*)x_paper, (uint2*)xb, n1);
    }

    // 1: all weight conversions
    {
        W2B b = {};
        const float* srcs[9] = {lin_paper_w, c0_root_paper_w, c0_root_author_w,
                                c0_rel_writes_w, c0_rel_cites_w, c0_rel_revw_w,
                                c1_root_w, c1_rel_writes_w, c1_rel_cites_w};
        __nv_bfloat16* dsts[9] = {wlin, w0rp, w0ra, w0w, w0c, w0r, w1rt, w1w, w1c};
        int Ns[9]    = {H_C, H_C, H_C, H_C, H_C, H_C, OUT_C, OUT_C, OUT_C};
        int Npads[9] = {H_C, H_C, H_C, H_C, H_C, H_C, 352, 352, 352};
        int Ks[9]    = {IN_C, H_C, H_C, H_C, H_C, H_C, H_C, H_C, H_C};
        int cum = 0;
        for (int q = 0; q < 9; q++) {
            b.src[q] = srcs[q]; b.dst[q] = dsts[q];
            b.N[q] = Ns[q]; b.Npad[q] = Npads[q];
            b.cum[q] = cum; cum += Ks[q] * Npads[q];
        }
        b.cum[9] = cum;
        w2b_all_kernel<<<(cum + 255) / 256, 256>>>(b);
    }

    // 2: zero count arrays
    {
        int na4 = P_N / 4, nb4 = P_N / 4, nc4 = A_N / 4;
        fill3_kernel<<<(na4 + nb4 + nc4 + 255) / 256, 256>>>(
            (int4*)cntW, na4, (int4*)cntC, nb4, (int4*)cntR, nc4);
    }

    // 3: GEMM1 (hp = x@Wlin + b) — ncu-captured slot
    {
        GemmParams p = {};
        p.A[0] = xb; p.B[0] = wlin; p.K[0] = IN_C;
        p.nseg = 1; p.bias = lin_paper_b; p.C = hp; p.M = P_N; p.N = H_C; p.Npad = H_C;
        dim3 grid(H_C / BN, tiles_P);
        gemm_fused_kernel<false, true><<<grid, 256, GEMM_SMEM>>>(p);
    }

    // 4: all degree counts
    count3_kernel<<<(E_W + E_C + E_W + 255) / 256, 256>>>(
        writes_dst, E_W, cntW, cites_dst, E_C, cntC, revw_dst, E_W, cntR);

    // 5-8: merged scans + CSR builds
    scan1_3_kernel<<<2 * NB_P + NB_A, SCB>>>(cntW, cntC, cntR, bsum);
    scan2_3_kernel<<<1, SCB>>>(bsum);
    scan3_3_kernel<<<2 * NB_P + NB_A, SCB>>>(cntW, cntC, cntR, bsum,
                                             rpW, rpC, rpR, nxW, nxC, nxR);
    build3_kernel<<<(E_W + E_C + E_W + 255) / 256, 256>>>(
        writes_src, writes_dst, E_W, nxW, csW,
        cites_src, cites_dst, E_C, nxC, csC,
        revw_src, revw_dst, E_W, nxR, csR);

    // 9-11: layer-0 gathers (separate launches)
    run_gather(emba, rpW, csW, P_N, aggA);
    run_gather(hp,   rpC, csC, P_N, aggB);
    run_gather(hp,   rpR, csR, A_N, aggC);

    // 12: layer-0 paper GEMM
    {
        GemmParams p = {};
        p.A[0] = hp;   p.B[0] = w0rp; p.K[0] = H_C;
        p.A[1] = aggA; p.B[1] = w0w;  p.K[1] = H_C;
        p.A[2] = aggB; p.B[2] = w0c;  p.K[2] = H_C;
        p.nseg = 3; p.bias = c0_root_paper_b; p.C = outp; p.M = P_N; p.N = H_C; p.Npad = H_C;
        dim3 grid(H_C / BN, tiles_P);
        gemm_fused_kernel<true, true><<<grid, 256, GEMM_SMEM>>>(p);
    }

    // 13: layer-0 author GEMM
    {
        GemmParams q = {};
        q.A[0] = emba; q.B[0] = w0ra; q.K[0] = H_C;
        q.A[1] = aggC; q.B[1] = w0r;  q.K[1] = H_C;
        q.nseg = 2; q.bias = c0_root_author_b; q.C = outa; q.M = A_N; q.N = H_C; q.Npad = H_C;
        dim3 grid(H_C / BN, tiles_A);
        gemm_fused_kernel<true, true><<<grid, 256, GEMM_SMEM>>>(q);
    }

    // 14-15: layer-1 gathers
    run_gather(outa, rpW, csW, P_N, aggA);
    run_gather(outp, rpC, csC, P_N, aggB);

    // 16: final GEMM (fp32 out)
    {
        GemmParams p = {};
        p.A[0] = outp; p.B[0] = w1rt; p.K[0] = H_C;
        p.A[1] = aggA; p.B[1] = w1w;  p.K[1] = H_C;
        p.A[2] = aggB; p.B[2] = w1c;  p.K[2] = H_C;
        p.nseg = 3; p.bias = c1_root_b; p.C = out; p.M = P_N; p.N = OUT_C; p.Npad = 352;
        dim3 grid((OUT_C + BN - 1) / BN, tiles_P);
        gemm_fused_kernel<false, false><<<grid, 256, GEMM_SMEM>>>(p);
    }

    // 17: log_softmax
    log_softmax_kernel<<<P_N, 128>>>(out, OUT_C);
}

// round 15
// speedup vs baseline: 1.1763x; 1.0232x over previous
#include <cuda_runtime.h>
#include <cuda_bf16.h>
#include <cstdint>

// ---------------------------------------------------------------------------
// RGCN forward. CSR gather-mean (warp-per-row, bf16), pipelined bf16 HMMA
// GEMMs (BK=64, 3-stage cp.async, ldmatrix + frag double-buffer, staged
// epilogues). Two-stream fork/join: CSR chain and layer-1 cites-gather
// overlap with GEMMs. P=100000, A=50000, IN=128, H=256, OUT=349
// ---------------------------------------------------------------------------

#define P_N   100000
#define A_N   50000
#define IN_C  128
#define H_C   256
#define OUT_C 349
#define EW_MAX 600000
#define EC_MAX 1000000
#define NB_P  98
#define NB_A  49

// bf16 feature buffers
__device__ __nv_bfloat16 g_hp  [(size_t)P_N * H_C];
__device__ __nv_bfloat16 g_outp[(size_t)P_N * H_C];
__device__ __nv_bfloat16 g_outa[(size_t)A_N * H_C];
__device__ __nv_bfloat16 g_aggA[(size_t)P_N * H_C];
__device__ __nv_bfloat16 g_aggB[(size_t)P_N * H_C];
__device__ __nv_bfloat16 g_aggC[(size_t)A_N * H_C];
__device__ __nv_bfloat16 g_emba[(size_t)A_N * H_C];
__device__ __nv_bfloat16 g_xb  [(size_t)P_N * IN_C];

// bf16 weights (padded to Npad columns)
__device__ __nv_bfloat16 g_wlin [IN_C * H_C];
__device__ __nv_bfloat16 g_w0rp [H_C * H_C];
__device__ __nv_bfloat16 g_w0ra [H_C * H_C];
__device__ __nv_bfloat16 g_w0w  [H_C * H_C];
__device__ __nv_bfloat16 g_w0c  [H_C * H_C];
__device__ __nv_bfloat16 g_w0r  [H_C * H_C];
__device__ __nv_bfloat16 g_w1rt [H_C * 352];
__device__ __nv_bfloat16 g_w1w  [H_C * 352];
__device__ __nv_bfloat16 g_w1c  [H_C * 352];

// CSR scratch
__device__ int g_cntW[P_N], g_cntC[P_N], g_cntR[A_N];
__device__ int g_rpW[P_N + 1], g_rpC[P_N + 1], g_rpR[A_N + 1];
__device__ int g_nxW[P_N], g_nxC[P_N], g_nxR[A_N];
__device__ int g_csW[EW_MAX], g_csC[EC_MAX], g_csR[EW_MAX];
__device__ int g_bsum[256];

// ---------------------------------------------------------------------------
__global__ void fill3_kernel(int4* a, int na4, int4* b, int nb4, int4* c, int nc4) {
    int i = blockIdx.x * blockDim.x + threadIdx.x;
    int4 z = make_int4(0, 0, 0, 0);
    if (i < na4) a[i] = z;
    else if (i < na4 + nb4) b[i - na4] = z;
    else if (i < na4 + nb4 + nc4) c[i - na4 - nb4] = z;
}

__global__ void count3_kernel(const int* __restrict__ wdst, int EW, int* __restrict__ cntW,
                              const int* __restrict__ cdst, int EC, int* __restrict__ cntC,
                              const int* __restrict__ rdst, int ER, int* __restrict__ cntR) {
    int i = blockIdx.x * blockDim.x + threadIdx.x;
    if (i < EW) atomicAdd(&cntW[wdst[i]], 1);
    else if (i < EW + EC) atomicAdd(&cntC[cdst[i - EW]], 1);
    else if (i < EW + EC + ER) atomicAdd(&cntR[rdst[i - EW - EC]], 1);
}

// ---------------------------------------------------------------------------
#define SCB 1024

__global__ void scan1_3_kernel(const int* __restrict__ cW, const int* __restrict__ cC,
                               const int* __restrict__ cR, int* __restrict__ bsum) {
    int b = blockIdx.x;
    const int* cnt; int n, base, lb;
    if (b < NB_P)           { cnt = cW; n = P_N; base = 0;        lb = b; }
    else if (b < 2 * NB_P)  { cnt = cC; n = P_N; base = NB_P;     lb = b - NB_P; }
    else                    { cnt = cR; n = A_N; base = 2 * NB_P; lb = b - 2 * NB_P; }
    __shared__ int sh[SCB];
    int tid = threadIdx.x;
    int i = lb * SCB + tid;
    sh[tid] = (i < n) ? cnt[i] : 0;
    __syncthreads();
    for (int off = SCB / 2; off; off >>= 1) {
        if (tid < off) sh[tid] += sh[tid + off];
        __syncthreads();
    }
    if (!tid) bsum[base + lb] = sh[0];
}

__global__ void scan2_3_kernel(int* __restrict__ bsum) {
    __shared__ int sh[SCB];
    int tid = threadIdx.x;
    int bases[3] = {0, NB_P, 2 * NB_P};
    int nbs[3]   = {NB_P, NB_P, NB_A};
#pragma unroll
    for (int r = 0; r < 3; r++) {
        int nb = nbs[r];
        int v = (tid < nb) ? bsum[bases[r] + tid] : 0;
        sh[tid] = v;
        __syncthreads();
        for (int off = 1; off < SCB; off <<= 1) {
            int a = (tid >= off) ? sh[tid - off] : 0;
            __syncthreads();
            sh[tid] += a;
            __syncthreads();
        }
        if (tid < nb) bsum[bases[r] + tid] = sh[tid] - v;
        __syncthreads();
    }
}

__global__ void scan3_3_kernel(const int* __restrict__ cW, const int* __restrict__ cC,
                               const int* __restrict__ cR, const int* __restrict__ bsum,
                               int* __restrict__ rpW, int* __restrict__ rpC, int* __restrict__ rpR,
                               int* __restrict__ nxW, int* __restrict__ nxC, int* __restrict__ nxR) {
    int b = blockIdx.x;
    const int* cnt; int n, base, lb; int *rowptr, *nextp;
    if (b < NB_P)          { cnt = cW; n = P_N; base = 0;        lb = b;            rowptr = rpW; nextp = nxW; }
    else if (b < 2 * NB_P) { cnt = cC; n = P_N; base = NB_P;     lb = b - NB_P;     rowptr = rpC; nextp = nxC; }
    else                   { cnt = cR; n = A_N; base = 2 * NB_P; lb = b - 2 * NB_P; rowptr = rpR; nextp = nxR; }
    __shared__ int sh[SCB];
    int tid = threadIdx.x;
    int i = lb * SCB + tid;
    int v = (i < n) ? cnt[i] : 0;
    sh[tid] = v;
    __syncthreads();
    for (int off = 1; off < SCB; off <<= 1) {
        int a = (tid >= off) ? sh[tid - off] : 0;
        __syncthreads();
        sh[tid] += a;
        __syncthreads();
    }
    int excl = sh[tid] - v + bsum[base + lb];
    if (i < n) { rowptr[i] = excl; nextp[i] = excl; }
    if (i == n - 1) rowptr[n] = excl + v;
}

__global__ void build3_kernel(const int* __restrict__ wsrc, const int* __restrict__ wdst, int EW,
                              int* __restrict__ nxW, int* __restrict__ csW,
                              const int* __restrict__ csrc, const int* __restrict__ cdst, int EC,
                              int* __restrict__ nxC, int* __restrict__ csC,
                              const int* __restrict__ rsrc, const int* __restrict__ rdst, int ER,
                              int* __restrict__ nxR, int* __restrict__ csR) {
    int i = blockIdx.x * blockDim.x + threadIdx.x;
    if (i < EW) {
        int p = atomicAdd(&nxW[wdst[i]], 1); csW[p] = wsrc[i];
    } else if (i < EW + EC) {
        int k = i - EW;
        int p = atomicAdd(&nxC[cdst[k]], 1); csC[p] = csrc[k];
    } else if (i < EW + EC + ER) {
        int k = i - EW - EC;
        int p = atomicAdd(&nxR[rdst[k]], 1); csR[p] = rsrc[k];
    }
}

// ---------------------------------------------------------------------------
__global__ void f2b_all_kernel(const float4* __restrict__ in0, uint2* __restrict__ out0, int n0,
                               const float4* __restrict__ in1, uint2* __restrict__ out1, int n1) {
    int i = blockIdx.x * blockDim.x + threadIdx.x;
    const float4* in; uint2* out; int k;
    if (i < n0)           { in = in0; out = out0; k = i; }
    else if (i < n0 + n1) { in = in1; out = out1; k = i - n0; }
    else return;
    float4 v = in[k];
    __nv_bfloat162 a = __floats2bfloat162_rn(v.x, v.y);
    __nv_bfloat162 b = __floats2bfloat162_rn(v.z, v.w);
    uint2 o;
    o.x = *(uint32_t*)&a;
    o.y = *(uint32_t*)&b;
    out[k] = o;
}

struct W2B {
    const float* src[9];
    __nv_bfloat16* dst[9];
    int N[9];
    int Npad[9];
    int cum[10];
};
__global__ void w2b_all_kernel(W2B b) {
    int i = blockIdx.x * blockDim.x + threadIdx.x;
    if (i >= b.cum[9]) return;
    int r = 0;
#pragma unroll
    for (int q = 0; q < 8; q++) if (i >= b.cum[q + 1]) r = q + 1;
    int local = i - b.cum[r];
    int Npad = b.Npad[r], N = b.N[r];
    int k = local / Npad, c = local - k * Npad;
    b.dst[r][local] = __float2bfloat16(c < N ? b.src[r][k * N + c] : 0.f);
}

// ---------------------------------------------------------------------------
// Gather-mean (bf16 in/out, fp32 accumulation). One warp per dst row.
// ---------------------------------------------------------------------------
__device__ __forceinline__ void acc8(float* s, uint4 u) {
    float2 f0 = __bfloat1622float2(*(__nv_bfloat162*)&u.x);
    float2 f1 = __bfloat1622float2(*(__nv_bfloat162*)&u.y);
    float2 f2 = __bfloat1622float2(*(__nv_bfloat162*)&u.z);
    float2 f3 = __bfloat1622float2(*(__nv_bfloat162*)&u.w);
    s[0] += f0.x; s[1] += f0.y; s[2] += f1.x; s[3] += f1.y;
    s[4] += f2.x; s[5] += f2.y; s[6] += f3.x; s[7] += f3.y;
}

__global__ void gather_mean_kernel(const __nv_bfloat16* __restrict__ feat,
                                   const int* __restrict__ rowptr,
                                   const int* __restrict__ csr_src,
                                   int num_dst,
                                   __nv_bfloat16* __restrict__ agg) {
    int group = blockIdx.x * 8 + (threadIdx.x >> 5);
    int lane  = threadIdx.x & 31;
    if (group >= num_dst) return;
    int beg = rowptr[group], end = rowptr[group + 1];
    int c8 = lane * 8;

    float s[8] = {0.f, 0.f, 0.f, 0.f, 0.f, 0.f, 0.f, 0.f};
    int i = beg;
    for (; i + 1 < end; i += 2) {
        int sa = csr_src[i];
        int sb = csr_src[i + 1];
        uint4 ua = *(const uint4*)&feat[(size_t)sa * H_C + c8];
        uint4 ub = *(const uint4*)&feat[(size_t)sb * H_C + c8];
        acc8(s, ua);
        acc8(s, ub);
    }
    if (i < end) {
        uint4 ua = *(const uint4*)&feat[(size_t)csr_src[i] * H_C + c8];
        acc8(s, ua);
    }
    float inv = (end > beg) ? 1.0f / (float)(end - beg) : 0.f;
    __nv_bfloat162 o0 = __floats2bfloat162_rn(s[0] * inv, s[1] * inv);
    __nv_bfloat162 o1 = __floats2bfloat162_rn(s[2] * inv, s[3] * inv);
    __nv_bfloat162 o2 = __floats2bfloat162_rn(s[4] * inv, s[5] * inv);
    __nv_bfloat162 o3 = __floats2bfloat162_rn(s[6] * inv, s[7] * inv);
    uint4 o;
    o.x = *(uint32_t*)&o0; o.y = *(uint32_t*)&o1;
    o.z = *(uint32_t*)&o2; o.w = *(uint32_t*)&o3;
    *(uint4*)&agg[(size_t)group * H_C + c8] = o;
}

// ---------------------------------------------------------------------------
// Pipelined fused multi-segment bf16 GEMM, BK=64, 3-stage cp.async,
// register fragment double-buffer, staged epilogue.
// ---------------------------------------------------------------------------
#define BM 128
#define BN 128
#define BK 64
#define PK 72
#define PN 136
#define A_BYTES (BM * PK * 2)
#define B_BYTES (BK * PN * 2)
#define STAGE_BYTES (A_BYTES + B_BYTES)     // 35840
#define NSTAGE 3
#define GEMM_SMEM (NSTAGE * STAGE_BYTES)    // 107520

struct GemmParams {
    const __nv_bfloat16* A[3];
    const __nv_bfloat16* B[3];
    int          K[3];
    int          nseg;
    const float* bias;
    void*        C;
    int          M, N, Npad;
};

__device__ __forceinline__ void cp16(uint32_t dst, const void* src, bool pred) {
    int sz = pred ? 16 : 0;
    asm volatile("cp.async.cg.shared.global [%0], [%1], 16, %2;"
                 :: "r"(dst), "l"(src), "r"(sz));
}

template<bool RELU, bool OUTBF16>
__device__ __forceinline__ void gemm_body(const GemmParams& p, int by) {
    extern __shared__ __align__(16) unsigned char smem_raw[];

    const int t    = threadIdx.x;
    const int lane = t & 31;
    const int w    = t >> 5;
    const int wm   = w & 1;
    const int wn   = w >> 1;
    const int g    = lane >> 2;
    const int tq   = lane & 3;
    const int row0 = by * BM;
    const int col0 = blockIdx.x * BN;
    const int M = p.M, N = p.N, Npad = p.Npad;
    const int nseg = p.nseg;

    const int kt0 = p.K[0] >> 6;
    const int kt1 = (nseg > 1) ? (p.K[1] >> 6) : 0;
    const int kt2 = (nseg > 2) ? (p.K[2] >> 6) : 0;
    const int total = kt0 + kt1 + kt2;

    const uint32_t smBase = (uint32_t)__cvta_generic_to_shared(smem_raw);

    const uint32_t aBase = smBase +
        (uint32_t)(((wm * 64 + (lane & 15)) * PK + ((lane >> 4) << 3)) << 1);
    const uint32_t bBase = smBase + A_BYTES +
        (uint32_t)(((lane & 15) * PN + wn * 32 + ((lane >> 4) << 3)) << 1);

    float acc[4][4][4];
#pragma unroll
    for (int i = 0; i < 4; i++)
#pragma unroll
        for (int j = 0; j < 4; j++)
#pragma unroll
            for (int v = 0; v < 4; v++) acc[i][j][v] = 0.f;

    auto issue = [&](int ti) {
        int s = 0, rem = ti;
        if (rem >= kt0)           { rem -= kt0; s = 1; }
        if (s == 1 && rem >= kt1) { rem -= kt1; s = 2; }
        int k0 = rem * BK;
        const __nv_bfloat16* A = p.A[s];
        const __nv_bfloat16* B = p.B[s];
        int K = p.K[s];
        uint32_t sb = smBase + (uint32_t)((ti % NSTAGE) * STAGE_BYTES);
#pragma unroll
        for (int it = 0; it < 4; it++) {
            int idx = t + it * 256;
            int r   = idx >> 3;
            int c8  = (idx & 7) * 8;
            int gr  = row0 + r;
            bool ok = (gr < M);
            int  sr = ok ? gr : 0;
            uint32_t dst = sb + (uint32_t)((r * PK + c8) << 1);
            cp16(dst, A + (size_t)sr * K + k0 + c8, ok);
        }
#pragma unroll
        for (int it = 0; it < 4; it++) {
            int idx = t + it * 256;
            int kr  = idx >> 4;
            int c8  = (idx & 15) * 8;
            int gc  = col0 + c8;
            bool ok = (gc < Npad);
            int  sc = ok ? gc : 0;
            uint32_t dst = sb + A_BYTES + (uint32_t)((kr * PN + c8) << 1);
            cp16(dst, B + (size_t)(k0 + kr) * Npad + sc, ok);
        }
        asm volatile("cp.async.commit_group;");
    };

    auto load_frags = [&](uint32_t so, int ko, uint32_t (*af)[4], uint32_t (*bf)[4]) {
#pragma unroll
        for (int i = 0; i < 4; i++) {
            uint32_t addr = aBase + so + (uint32_t)(((i * 16) * PK + ko) << 1);
            asm volatile("ldmatrix.sync.aligned.m8n8.x4.shared.b16 {%0,%1,%2,%3}, [%4];"
                         : "=r"(af[i][0]), "=r"(af[i][1]), "=r"(af[i][2]), "=r"(af[i][3])
                         : "r"(addr));
        }
#pragma unroll
        for (int jj = 0; jj < 2; jj++) {
            uint32_t addr = bBase + so + (uint32_t)((ko * PN + jj * 16) << 1);
            asm volatile("ldmatrix.sync.aligned.m8n8.x4.trans.shared.b16 {%0,%1,%2,%3}, [%4];"
                         : "=r"(bf[jj][0]), "=r"(bf[jj][1]), "=r"(bf[jj][2]), "=r"(bf[jj][3])
                         : "r"(addr));
        }
    };

    issue(0);
    if (total > 1) issue(1);

    uint32_t afr[2][4][4];
    uint32_t bfr[2][2][4];

    for (int ti = 0; ti < total; ti++) {
        if (ti + 2 < total) {
            issue(ti + 2);
            asm volatile("cp.async.wait_group 2;");
        } else if (ti + 1 < total) {
            asm volatile("cp.async.wait_group 1;");
        } else {
            asm volatile("cp.async.wait_group 0;");
        }
        __syncthreads();

        const uint32_t so = (uint32_t)((ti % NSTAGE) * STAGE_BYTES);

        load_frags(so, 0, afr[0], bfr[0]);
#pragma unroll
        for (int ks = 0; ks < 4; ks++) {
            const int cur = ks & 1;
            const int nxt = cur ^ 1;
            if (ks < 3) load_frags(so, (ks + 1) * 16, afr[nxt], bfr[nxt]);
#pragma unroll
            for (int i = 0; i < 4; i++)
#pragma unroll
                for (int j = 0; j < 4; j++) {
                    uint32_t b0 = bfr[cur][j >> 1][(j & 1) * 2];
                    uint32_t b1 = bfr[cur][j >> 1][(j & 1) * 2 + 1];
                    asm volatile(
                        "mma.sync.aligned.m16n8k16.row.col.f32.bf16.bf16.f32 "
                        "{%0,%1,%2,%3}, {%4,%5,%6,%7}, {%8,%9}, {%0,%1,%2,%3};\n"
                        : "+f"(acc[i][j][0]), "+f"(acc[i][j][1]),
                          "+f"(acc[i][j][2]), "+f"(acc[i][j][3])
                        : "r"(afr[cur][i][0]), "r"(afr[cur][i][1]),
                          "r"(afr[cur][i][2]), "r"(afr[cur][i][3]),
                          "r"(b0), "r"(b1));
                }
        }
        __syncthreads();
    }

    // ---- staged epilogue: coalesced global stores ----
    __syncthreads();
    if (OUTBF16) {
        __nv_bfloat16* cs = (__nv_bfloat16*)smem_raw;   // [128][136]
        __nv_bfloat16* Cb = (__nv_bfloat16*)p.C;
#pragma unroll
        for (int i = 0; i < 4; i++) {
            int r0l = wm * 64 + i * 16 + g;
#pragma unroll
            for (int j = 0; j < 4; j++) {
                int cl = wn * 32 + j * 8 + tq * 2;
                float bv0 = p.bias[col0 + cl];
                float bv1 = p.bias[col0 + cl + 1];
                float x0 = acc[i][j][0] + bv0, x1 = acc[i][j][1] + bv1;
                float y0 = acc[i][j][2] + bv0, y1 = acc[i][j][3] + bv1;
                if (RELU) {
                    x0 = fmaxf(x0, 0.f); x1 = fmaxf(x1, 0.f);
                    y0 = fmaxf(y0, 0.f); y1 = fmaxf(y1, 0.f);
                }
                *(__nv_bfloat162*)&cs[r0l * 136 + cl]       = __floats2bfloat162_rn(x0, x1);
                *(__nv_bfloat162*)&cs[(r0l + 8) * 136 + cl] = __floats2bfloat162_rn(y0, y1);
            }
        }
        __syncthreads();
#pragma unroll
        for (int it = 0; it < 8; it++) {
            int idx = t + it * 256;
            int r   = idx >> 4;
            int c8  = (idx & 15) * 8;
            int gr  = row0 + r;
            int gc  = col0 + c8;
            if (gr < M) {
                if (gc + 8 <= N) {
                    *(uint4*)&Cb[(size_t)gr * N + gc] = *(uint4*)&cs[r * 136 + c8];
                } else {
                    for (int e = 0; e < 8; e++)
                        if (gc + e < N) Cb[(size_t)gr * N + gc + e] = cs[r * 136 + c8 + e];
                }
            }
        }
    } else {
        float* cs = (float*)smem_raw;   // [64][132] per half
        float* Cf = (float*)p.C;
#pragma unroll
        for (int half = 0; half < 2; half++) {
            __syncthreads();
            if (wm == half) {
#pragma unroll
                for (int i = 0; i < 4; i++) {
                    int r0l = i * 16 + g;
#pragma unroll
                    for (int j = 0; j < 4; j++) {
                        int cl = wn * 32 + j * 8 + tq * 2;
                        float bv0 = p.bias[col0 + cl];
                        float bv1 = p.bias[col0 + cl + 1];
                        cs[r0l * 132 + cl]           = acc[i][j][0] + bv0;
                        cs[r0l * 132 + cl + 1]       = acc[i][j][1] + bv1;
                        cs[(r0l + 8) * 132 + cl]     = acc[i][j][2] + bv0;
                        cs[(r0l + 8) * 132 + cl + 1] = acc[i][j][3] + bv1;
                    }
                }
            }
            __syncthreads();
#pragma unroll
            for (int it = 0; it < 32; it++) {
                int idx = t + it * 256;
                int r   = idx >> 7;
                int c   = idx & 127;
                int gr  = row0 + half * 64 + r;
                int gc  = col0 + c;
                if (gr < M && gc < N)
                    Cf[(size_t)gr * N + gc] = cs[r * 132 + c];
            }
        }
    }
}

template<bool RELU, bool OUTBF16>
__global__ __launch_bounds__(256, 2)
void gemm_fused_kernel(GemmParams p) {
    gemm_body<RELU, OUTBF16>(p, blockIdx.y);
}

// ---------------------------------------------------------------------------
__inline__ __device__ float warpMax(float v) {
#pragma unroll
    for (int o = 16; o; o >>= 1) v = fmaxf(v, __shfl_xor_sync(0xFFFFFFFFu, v, o));
    return v;
}
__inline__ __device__ float warpSum(float v) {
#pragma unroll
    for (int o = 16; o; o >>= 1) v += __shfl_xor_sync(0xFFFFFFFFu, v, o);
    return v;
}

__global__ void log_softmax_kernel(float* __restrict__ x, int N) {
    float* r = x + (size_t)blockIdx.x * N;
    int t = threadIdx.x;

    float m = -1e30f;
    for (int i = t; i < N; i += 128) m = fmaxf(m, r[i]);
    m = warpMax(m);
    __shared__ float shm[4];
    if ((t & 31) == 0) shm[t >> 5] = m;
    __syncthreads();
    m = fmaxf(fmaxf(shm[0], shm[1]), fmaxf(shm[2], shm[3]));

    float s = 0.f;
    for (int i = t; i < N; i += 128) s += expf(r[i] - m);
    s = warpSum(s);
    __shared__ float shs[4];
    if ((t & 31) == 0) shs[t >> 5] = s;
    __syncthreads();
    s = shs[0] + shs[1] + shs[2] + shs[3];

    float lse = m + logf(s);
    for (int i = t; i < N; i += 128) r[i] = r[i] - lse;
}

// ---------------------------------------------------------------------------
extern "C" void kernel_launch(void* const* d_in, const int* in_sizes, int n_in,
                              void* d_out, int out_size) {
    const float* x_paper          = (const float*)d_in[0];
    const float* emb_author       = (const float*)d_in[1];
    const float* lin_paper_w      = (const float*)d_in[2];
    const float* lin_paper_b      = (const float*)d_in[3];
    const float* c0_root_paper_w  = (const float*)d_in[4];
    const float* c0_root_paper_b  = (const float*)d_in[5];
    const float* c0_root_author_w = (const float*)d_in[6];
    const float* c0_root_author_b = (const float*)d_in[7];
    const float* c0_rel_writes_w  = (const float*)d_in[8];
    const float* c0_rel_cites_w   = (const float*)d_in[9];
    const float* c0_rel_revw_w    = (const float*)d_in[10];
    const float* c1_root_w        = (const float*)d_in[11];
    const float* c1_root_b        = (const float*)d_in[12];
    const float* c1_rel_writes_w  = (const float*)d_in[13];
    const float* c1_rel_cites_w   = (const float*)d_in[14];
    const int*   writes_src       = (const int*)d_in[15];
    const int*   writes_dst       = (const int*)d_in[16];
    const int*   cites_src        = (const int*)d_in[17];
    const int*   cites_dst        = (const int*)d_in[18];
    const int*   revw_src         = (const int*)d_in[19];
    const int*   revw_dst         = (const int*)d_in[20];

    const int E_W = in_sizes[15];
    const int E_C = in_sizes[17];
    float* out = (float*)d_out;

    __nv_bfloat16 *hp, *outp, *outa, *aggA, *aggB, *aggC, *emba, *xb;
    __nv_bfloat16 *wlin, *w0rp, *w0ra, *w0w, *w0c, *w0r, *w1rt, *w1w, *w1c;
    int *cntW, *cntC, *cntR, *rpW, *rpC, *rpR, *nxW, *nxC, *nxR, *csW, *csC, *csR, *bsum;
    cudaGetSymbolAddress((void**)&hp,   g_hp);
    cudaGetSymbolAddress((void**)&outp, g_outp);
    cudaGetSymbolAddress((void**)&outa, g_outa);
    cudaGetSymbolAddress((void**)&aggA, g_aggA);
    cudaGetSymbolAddress((void**)&aggB, g_aggB);
    cudaGetSymbolAddress((void**)&aggC, g_aggC);
    cudaGetSymbolAddress((void**)&emba, g_emba);
    cudaGetSymbolAddress((void**)&xb,   g_xb);
    cudaGetSymbolAddress((void**)&wlin, g_wlin);
    cudaGetSymbolAddress((void**)&w0rp, g_w0rp);
    cudaGetSymbolAddress((void**)&w0ra, g_w0ra);
    cudaGetSymbolAddress((void**)&w0w,  g_w0w);
    cudaGetSymbolAddress((void**)&w0c,  g_w0c);
    cudaGetSymbolAddress((void**)&w0r,  g_w0r);
    cudaGetSymbolAddress((void**)&w1rt, g_w1rt);
    cudaGetSymbolAddress((void**)&w1w,  g_w1w);
    cudaGetSymbolAddress((void**)&w1c,  g_w1c);
    cudaGetSymbolAddress((void**)&cntW, g_cntW);
    cudaGetSymbolAddress((void**)&cntC, g_cntC);
    cudaGetSymbolAddress((void**)&cntR, g_cntR);
    cudaGetSymbolAddress((void**)&rpW,  g_rpW);
    cudaGetSymbolAddress((void**)&rpC,  g_rpC);
    cudaGetSymbolAddress((void**)&rpR,  g_rpR);
    cudaGetSymbolAddress((void**)&nxW,  g_nxW);
    cudaGetSymbolAddress((void**)&nxC,  g_nxC);
    cudaGetSymbolAddress((void**)&nxR,  g_nxR);
    cudaGetSymbolAddress((void**)&csW,  g_csW);
    cudaGetSymbolAddress((void**)&csC,  g_csC);
    cudaGetSymbolAddress((void**)&csR,  g_csR);
    cudaGetSymbolAddress((void**)&bsum, g_bsum);

    cudaFuncSetAttribute(gemm_fused_kernel<false, true >, cudaFuncAttributeMaxDynamicSharedMemorySize, GEMM_SMEM);
    cudaFuncSetAttribute(gemm_fused_kernel<true,  true >, cudaFuncAttributeMaxDynamicSharedMemorySize, GEMM_SMEM);
    cudaFuncSetAttribute(gemm_fused_kernel<false, false>, cudaFuncAttributeMaxDynamicSharedMemorySize, GEMM_SMEM);

    const int tiles_P = (P_N + BM - 1) / BM;   // 782
    const int tiles_A = (A_N + BM - 1) / BM;   // 391

    // Side stream + events (host-side objects only; kernel_launch runs only a
    // few times — correctness + capture — so per-call creation is fine).
    cudaStream_t s2;
    cudaStreamCreateWithFlags(&s2, cudaStreamNonBlocking);
    cudaEvent_t eFork, eF2B, eCSR, eAggA, eG2, eB2;
    cudaEventCreateWithFlags(&eFork, cudaEventDisableTiming);
    cudaEventCreateWithFlags(&eF2B,  cudaEventDisableTiming);
    cudaEventCreateWithFlags(&eCSR,  cudaEventDisableTiming);
    cudaEventCreateWithFlags(&eAggA, cudaEventDisableTiming);
    cudaEventCreateWithFlags(&eG2,   cudaEventDisableTiming);
    cudaEventCreateWithFlags(&eB2,   cudaEventDisableTiming);

    // ---- fork side stream from the capture stream ----
    cudaEventRecord(eFork, 0);
    cudaStreamWaitEvent(s2, eFork, 0);

    // ================= SIDE STREAM: CSR chain + writes-gather =================
    {
        int na4 = P_N / 4, nb4 = P_N / 4, nc4 = A_N / 4;
        fill3_kernel<<<(na4 + nb4 + nc4 + 255) / 256, 256, 0, s2>>>(
            (int4*)cntW, na4, (int4*)cntC, nb4, (int4*)cntR, nc4);
    }
    count3_kernel<<<(E_W + E_C + E_W + 255) / 256, 256, 0, s2>>>(
        writes_dst, E_W, cntW, cites_dst, E_C, cntC, revw_dst, E_W, cntR);
    scan1_3_kernel<<<2 * NB_P + NB_A, SCB, 0, s2>>>(cntW, cntC, cntR, bsum);
    scan2_3_kernel<<<1, SCB, 0, s2>>>(bsum);
    scan3_3_kernel<<<2 * NB_P + NB_A, SCB, 0, s2>>>(cntW, cntC, cntR, bsum,
                                                    rpW, rpC, rpR, nxW, nxC, nxR);
    build3_kernel<<<(E_W + E_C + E_W + 255) / 256, 256, 0, s2>>>(
        writes_src, writes_dst, E_W, nxW, csW,
        cites_src, cites_dst, E_C, nxC, csC,
        revw_src, revw_dst, E_W, nxR, csR);
    cudaEventRecord(eCSR, s2);

    // ================= MAIN STREAM: conversions + GEMM1 =================
    {
        int n0 = A_N * H_C / 4, n1 = P_N * IN_C / 4;
        f2b_all_kernel<<<(n0 + n1 + 255) / 256, 256>>>(
            (const float4*)emb_author, (uint2*)emba, n0,
            (const float4*)x_paper, (uint2*)xb, n1);
    }
    cudaEventRecord(eF2B, 0);
    {
        W2B b = {};
        const float* srcs[9] = {lin_paper_w, c0_root_paper_w, c0_root_author_w,
                                c0_rel_writes_w, c0_rel_cites_w, c0_rel_revw_w,
                                c1_root_w, c1_rel_writes_w, c1_rel_cites_w};
        __nv_bfloat16* dsts[9] = {wlin, w0rp, w0ra, w0w, w0c, w0r, w1rt, w1w, w1c};
        int Ns[9]    = {H_C, H_C, H_C, H_C, H_C, H_C, OUT_C, OUT_C, OUT_C};
        int Npads[9] = {H_C, H_C, H_C, H_C, H_C, H_C, 352, 352, 352};
        int Ks[9]    = {IN_C, H_C, H_C, H_C, H_C, H_C, H_C, H_C, H_C};
        int cum = 0;
        for (int q = 0; q < 9; q++) {
            b.src[q] = srcs[q]; b.dst[q] = dsts[q];
            b.N[q] = Ns[q]; b.Npad[q] = Npads[q];
            b.cum[q] = cum; cum += Ks[q] * Npads[q];
        }
        b.cum[9] = cum;
        w2b_all_kernel<<<(cum + 255) / 256, 256>>>(b);
    }
    {
        GemmParams p = {};
        p.A[0] = xb; p.B[0] = wlin; p.K[0] = IN_C;
        p.nseg = 1; p.bias = lin_paper_b; p.C = hp; p.M = P_N; p.N = H_C; p.Npad = H_C;
        dim3 grid(H_C / BN, tiles_P);
        gemm_fused_kernel<false, true><<<grid, 256, GEMM_SMEM>>>(p);
    }

    // SIDE: writes-gather (needs emba from f2b + csW from build3)
    cudaStreamWaitEvent(s2, eF2B, 0);
    gather_mean_kernel<<<(P_N + 7) / 8, 256, 0, s2>>>(emba, rpW, csW, P_N, aggA);
    cudaEventRecord(eAggA, s2);

    // MAIN: cites/revw gathers (need hp + CSRs)
    cudaStreamWaitEvent(0, eCSR, 0);
    gather_mean_kernel<<<(P_N + 7) / 8, 256>>>(hp, rpC, csC, P_N, aggB);
    gather_mean_kernel<<<(A_N + 7) / 8, 256>>>(hp, rpR, csR, A_N, aggC);

    // MAIN: layer-0 paper GEMM (needs aggA from side)
    cudaStreamWaitEvent(0, eAggA, 0);
    {
        GemmParams p = {};
        p.A[0] = hp;   p.B[0] = w0rp; p.K[0] = H_C;
        p.A[1] = aggA; p.B[1] = w0w;  p.K[1] = H_C;
        p.A[2] = aggB; p.B[2] = w0c;  p.K[2] = H_C;
        p.nseg = 3; p.bias = c0_root_paper_b; p.C = outp; p.M = P_N; p.N = H_C; p.Npad = H_C;
        dim3 grid(H_C / BN, tiles_P);
        gemm_fused_kernel<true, true><<<grid, 256, GEMM_SMEM>>>(p);
    }
    cudaEventRecord(eG2, 0);

    // SIDE: layer-1 cites-gather (outp ready after GEMM2; overwrites aggB
    // only after GEMM2 has consumed it)
    cudaStreamWaitEvent(s2, eG2, 0);
    gather_mean_kernel<<<(P_N + 7) / 8, 256, 0, s2>>>(outp, rpC, csC, P_N, aggB);
    cudaEventRecord(eB2, s2);

    // MAIN: layer-0 author GEMM (independent of side's gather)
    {
        GemmParams q = {};
        q.A[0] = emba; q.B[0] = w0ra; q.K[0] = H_C;
        q.A[1] = aggC; q.B[1] = w0r;  q.K[1] = H_C;
        q.nseg = 2; q.bias = c0_root_author_b; q.C = outa; q.M = A_N; q.N = H_C; q.Npad = H_C;
        dim3 grid(H_C / BN, tiles_A);
        gemm_fused_kernel<true, true><<<grid, 256, GEMM_SMEM>>>(q);
    }

    // MAIN: layer-1 writes-gather (needs outa; aggA already consumed by GEMM2)
    gather_mean_kernel<<<(P_N + 7) / 8, 256>>>(outa, rpW, csW, P_N, aggA);

    // ---- join side stream, final GEMM + softmax on main ----
    cudaStreamWaitEvent(0, eB2, 0);
    {
        GemmParams p = {};
        p.A[0] = outp; p.B[0] = w1rt; p.K[0] = H_C;
        p.A[1] = aggA; p.B[1] = w1w;  p.K[1] = H_C;
        p.A[2] = aggB; p.B[2] = w1c;  p.K[2] = H_C;
        p.nseg = 3; p.bias = c1_root_b; p.C = out; p.M = P_N; p.N = OUT_C; p.Npad = 352;
        dim3 grid((OUT_C + BN - 1) / BN, tiles_P);
        gemm_fused_kernel<false, false><<<grid, 256, GEMM_SMEM>>>(p);
    }
    log_softmax_kernel<<<P_N, 128>>>(out, OUT_C);
}

// round 16
// speedup vs baseline: 1.1975x; 1.0180x over previous
#include <cuda_runtime.h>
#include <cuda_bf16.h>
#include <cstdint>

// ---------------------------------------------------------------------------
// RGCN forward. CSR gather-mean (warp-per-row, bf16), pipelined bf16 HMMA
// GEMMs (BK=64, 3-stage cp.async, ldmatrix + frag double-buffer, staged
// epilogues). Two streams: author subgraph (gatherC, GEMM3, writes-gather)
// fully on the side stream; main stream carries only the critical path.
// P=100000, A=50000, IN=128, H=256, OUT=349
// ---------------------------------------------------------------------------

#define P_N   100000
#define A_N   50000
#define IN_C  128
#define H_C   256
#define OUT_C 349
#define EW_MAX 600000
#define EC_MAX 1000000
#define NB_P  98
#define NB_A  49

// bf16 feature buffers
__device__ __nv_bfloat16 g_hp  [(size_t)P_N * H_C];
__device__ __nv_bfloat16 g_outp[(size_t)P_N * H_C];
__device__ __nv_bfloat16 g_outa[(size_t)A_N * H_C];
__device__ __nv_bfloat16 g_aggA[(size_t)P_N * H_C];
__device__ __nv_bfloat16 g_aggB[(size_t)P_N * H_C];
__device__ __nv_bfloat16 g_aggC[(size_t)A_N * H_C];
__device__ __nv_bfloat16 g_aggD[(size_t)P_N * H_C];
__device__ __nv_bfloat16 g_emba[(size_t)A_N * H_C];
__device__ __nv_bfloat16 g_xb  [(size_t)P_N * IN_C];

// bf16 weights (padded to Npad columns)
__device__ __nv_bfloat16 g_wlin [IN_C * H_C];
__device__ __nv_bfloat16 g_w0rp [H_C * H_C];
__device__ __nv_bfloat16 g_w0ra [H_C * H_C];
__device__ __nv_bfloat16 g_w0w  [H_C * H_C];
__device__ __nv_bfloat16 g_w0c  [H_C * H_C];
__device__ __nv_bfloat16 g_w0r  [H_C * H_C];
__device__ __nv_bfloat16 g_w1rt [H_C * 352];
__device__ __nv_bfloat16 g_w1w  [H_C * 352];
__device__ __nv_bfloat16 g_w1c  [H_C * 352];

// CSR scratch
__device__ int g_cntW[P_N], g_cntC[P_N], g_cntR[A_N];
__device__ int g_rpW[P_N + 1], g_rpC[P_N + 1], g_rpR[A_N + 1];
__device__ int g_nxW[P_N], g_nxC[P_N], g_nxR[A_N];
__device__ int g_csW[EW_MAX], g_csC[EC_MAX], g_csR[EW_MAX];
__device__ int g_bsum[256];

// ---------------------------------------------------------------------------
__global__ void fill3_kernel(int4* a, int na4, int4* b, int nb4, int4* c, int nc4) {
    int i = blockIdx.x * blockDim.x + threadIdx.x;
    int4 z = make_int4(0, 0, 0, 0);
    if (i < na4) a[i] = z;
    else if (i < na4 + nb4) b[i - na4] = z;
    else if (i < na4 + nb4 + nc4) c[i - na4 - nb4] = z;
}

__global__ void count3_kernel(const int* __restrict__ wdst, int EW, int* __restrict__ cntW,
                              const int* __restrict__ cdst, int EC, int* __restrict__ cntC,
                              const int* __restrict__ rdst, int ER, int* __restrict__ cntR) {
    int i = blockIdx.x * blockDim.x + threadIdx.x;
    if (i < EW) atomicAdd(&cntW[wdst[i]], 1);
    else if (i < EW + EC) atomicAdd(&cntC[cdst[i - EW]], 1);
    else if (i < EW + EC + ER) atomicAdd(&cntR[rdst[i - EW - EC]], 1);
}

// ---------------------------------------------------------------------------
#define SCB 1024

__global__ void scan1_3_kernel(const int* __restrict__ cW, const int* __restrict__ cC,
                               const int* __restrict__ cR, int* __restrict__ bsum) {
    int b = blockIdx.x;
    const int* cnt; int n, base, lb;
    if (b < NB_P)           { cnt = cW; n = P_N; base = 0;        lb = b; }
    else if (b < 2 * NB_P)  { cnt = cC; n = P_N; base = NB_P;     lb = b - NB_P; }
    else                    { cnt = cR; n = A_N; base = 2 * NB_P; lb = b - 2 * NB_P; }
    __shared__ int sh[SCB];
    int tid = threadIdx.x;
    int i = lb * SCB + tid;
    sh[tid] = (i < n) ? cnt[i] : 0;
    __syncthreads();
    for (int off = SCB / 2; off; off >>= 1) {
        if (tid < off) sh[tid] += sh[tid + off];
        __syncthreads();
    }
    if (!tid) bsum[base + lb] = sh[0];
}

__global__ void scan2_3_kernel(int* __restrict__ bsum) {
    __shared__ int sh[SCB];
    int tid = threadIdx.x;
    int bases[3] = {0, NB_P, 2 * NB_P};
    int nbs[3]   = {NB_P, NB_P, NB_A};
#pragma unroll
    for (int r = 0; r < 3; r++) {
        int nb = nbs[r];
        int v = (tid < nb) ? bsum[bases[r] + tid] : 0;
        sh[tid] = v;
        __syncthreads();
        for (int off = 1; off < SCB; off <<= 1) {
            int a = (tid >= off) ? sh[tid - off] : 0;
            __syncthreads();
            sh[tid] += a;
            __syncthreads();
        }
        if (tid < nb) bsum[bases[r] + tid] = sh[tid] - v;
        __syncthreads();
    }
}

__global__ void scan3_3_kernel(const int* __restrict__ cW, const int* __restrict__ cC,
                               const int* __restrict__ cR, const int* __restrict__ bsum,
                               int* __restrict__ rpW, int* __restrict__ rpC, int* __restrict__ rpR,
                               int* __restrict__ nxW, int* __restrict__ nxC, int* __restrict__ nxR) {
    int b = blockIdx.x;
    const int* cnt; int n, base, lb; int *rowptr, *nextp;
    if (b < NB_P)          { cnt = cW; n = P_N; base = 0;        lb = b;            rowptr = rpW; nextp = nxW; }
    else if (b < 2 * NB_P) { cnt = cC; n = P_N; base = NB_P;     lb = b - NB_P;     rowptr = rpC; nextp = nxC; }
    else                   { cnt = cR; n = A_N; base = 2 * NB_P; lb = b - 2 * NB_P; rowptr = rpR; nextp = nxR; }
    __shared__ int sh[SCB];
    int tid = threadIdx.x;
    int i = lb * SCB + tid;
    int v = (i < n) ? cnt[i] : 0;
    sh[tid] = v;
    __syncthreads();
    for (int off = 1; off < SCB; off <<= 1) {
        int a = (tid >= off) ? sh[tid - off] : 0;
        __syncthreads();
        sh[tid] += a;
        __syncthreads();
    }
    int excl = sh[tid] - v + bsum[base + lb];
    if (i < n) { rowptr[i] = excl; nextp[i] = excl; }
    if (i == n - 1) rowptr[n] = excl + v;
}

__global__ void build3_kernel(const int* __restrict__ wsrc, const int* __restrict__ wdst, int EW,
                              int* __restrict__ nxW, int* __restrict__ csW,
                              const int* __restrict__ csrc, const int* __restrict__ cdst, int EC,
                              int* __restrict__ nxC, int* __restrict__ csC,
                              const int* __restrict__ rsrc, const int* __restrict__ rdst, int ER,
                              int* __restrict__ nxR, int* __restrict__ csR) {
    int i = blockIdx.x * blockDim.x + threadIdx.x;
    if (i < EW) {
        int p = atomicAdd(&nxW[wdst[i]], 1); csW[p] = wsrc[i];
    } else if (i < EW + EC) {
        int k = i - EW;
        int p = atomicAdd(&nxC[cdst[k]], 1); csC[p] = csrc[k];
    } else if (i < EW + EC + ER) {
        int k = i - EW - EC;
        int p = atomicAdd(&nxR[rdst[k]], 1); csR[p] = rsrc[k];
    }
}

// ---------------------------------------------------------------------------
__global__ void f2b_all_kernel(const float4* __restrict__ in0, uint2* __restrict__ out0, int n0,
                               const float4* __restrict__ in1, uint2* __restrict__ out1, int n1) {
    int i = blockIdx.x * blockDim.x + threadIdx.x;
    const float4* in; uint2* out; int k;
    if (i < n0)           { in = in0; out = out0; k = i; }
    else if (i < n0 + n1) { in = in1; out = out1; k = i - n0; }
    else return;
    float4 v = in[k];
    __nv_bfloat162 a = __floats2bfloat162_rn(v.x, v.y);
    __nv_bfloat162 b = __floats2bfloat162_rn(v.z, v.w);
    uint2 o;
    o.x = *(uint32_t*)&a;
    o.y = *(uint32_t*)&b;
    out[k] = o;
}

struct W2B {
    const float* src[9];
    __nv_bfloat16* dst[9];
    int N[9];
    int Npad[9];
    int cum[10];
};
__global__ void w2b_all_kernel(W2B b) {
    int i = blockIdx.x * blockDim.x + threadIdx.x;
    if (i >= b.cum[9]) return;
    int r = 0;
#pragma unroll
    for (int q = 0; q < 8; q++) if (i >= b.cum[q + 1]) r = q + 1;
    int local = i - b.cum[r];
    int Npad = b.Npad[r], N = b.N[r];
    int k = local / Npad, c = local - k * Npad;
    b.dst[r][local] = __float2bfloat16(c < N ? b.src[r][k * N + c] : 0.f);
}

// ---------------------------------------------------------------------------
// Gather-mean (bf16 in/out, fp32 accumulation). One warp per dst row.
// ---------------------------------------------------------------------------
__device__ __forceinline__ void acc8(float* s, uint4 u) {
    float2 f0 = __bfloat1622float2(*(__nv_bfloat162*)&u.x);
    float2 f1 = __bfloat1622float2(*(__nv_bfloat162*)&u.y);
    float2 f2 = __bfloat1622float2(*(__nv_bfloat162*)&u.z);
    float2 f3 = __bfloat1622float2(*(__nv_bfloat162*)&u.w);
    s[0] += f0.x; s[1] += f0.y; s[2] += f1.x; s[3] += f1.y;
    s[4] += f2.x; s[5] += f2.y; s[6] += f3.x; s[7] += f3.y;
}

__global__ void gather_mean_kernel(const __nv_bfloat16* __restrict__ feat,
                                   const int* __restrict__ rowptr,
                                   const int* __restrict__ csr_src,
                                   int num_dst,
                                   __nv_bfloat16* __restrict__ agg) {
    int group = blockIdx.x * 8 + (threadIdx.x >> 5);
    int lane  = threadIdx.x & 31;
    if (group >= num_dst) return;
    int beg = rowptr[group], end = rowptr[group + 1];
    int c8 = lane * 8;

    float s[8] = {0.f, 0.f, 0.f, 0.f, 0.f, 0.f, 0.f, 0.f};
    int i = beg;
    for (; i + 1 < end; i += 2) {
        int sa = csr_src[i];
        int sb = csr_src[i + 1];
        uint4 ua = *(const uint4*)&feat[(size_t)sa * H_C + c8];
        uint4 ub = *(const uint4*)&feat[(size_t)sb * H_C + c8];
        acc8(s, ua);
        acc8(s, ub);
    }
    if (i < end) {
        uint4 ua = *(const uint4*)&feat[(size_t)csr_src[i] * H_C + c8];
        acc8(s, ua);
    }
    float inv = (end > beg) ? 1.0f / (float)(end - beg) : 0.f;
    __nv_bfloat162 o0 = __floats2bfloat162_rn(s[0] * inv, s[1] * inv);
    __nv_bfloat162 o1 = __floats2bfloat162_rn(s[2] * inv, s[3] * inv);
    __nv_bfloat162 o2 = __floats2bfloat162_rn(s[4] * inv, s[5] * inv);
    __nv_bfloat162 o3 = __floats2bfloat162_rn(s[6] * inv, s[7] * inv);
    uint4 o;
    o.x = *(uint32_t*)&o0; o.y = *(uint32_t*)&o1;
    o.z = *(uint32_t*)&o2; o.w = *(uint32_t*)&o3;
    *(uint4*)&agg[(size_t)group * H_C + c8] = o;
}

// ---------------------------------------------------------------------------
// Pipelined fused multi-segment bf16 GEMM, BK=64, 3-stage cp.async,
// register fragment double-buffer, staged epilogue.
// ---------------------------------------------------------------------------
#define BM 128
#define BN 128
#define BK 64
#define PK 72
#define PN 136
#define A_BYTES (BM * PK * 2)
#define B_BYTES (BK * PN * 2)
#define STAGE_BYTES (A_BYTES + B_BYTES)     // 35840
#define NSTAGE 3
#define GEMM_SMEM (NSTAGE * STAGE_BYTES)    // 107520

struct GemmParams {
    const __nv_bfloat16* A[3];
    const __nv_bfloat16* B[3];
    int          K[3];
    int          nseg;
    const float* bias;
    void*        C;
    int          M, N, Npad;
};

__device__ __forceinline__ void cp16(uint32_t dst, const void* src, bool pred) {
    int sz = pred ? 16 : 0;
    asm volatile("cp.async.cg.shared.global [%0], [%1], 16, %2;"
                 :: "r"(dst), "l"(src), "r"(sz));
}

template<bool RELU, bool OUTBF16>
__device__ __forceinline__ void gemm_body(const GemmParams& p, int by) {
    extern __shared__ __align__(16) unsigned char smem_raw[];

    const int t    = threadIdx.x;
    const int lane = t & 31;
    const int w    = t >> 5;
    const int wm   = w & 1;
    const int wn   = w >> 1;
    const int g    = lane >> 2;
    const int tq   = lane & 3;
    const int row0 = by * BM;
    const int col0 = blockIdx.x * BN;
    const int M = p.M, N = p.N, Npad = p.Npad;
    const int nseg = p.nseg;

    const int kt0 = p.K[0] >> 6;
    const int kt1 = (nseg > 1) ? (p.K[1] >> 6) : 0;
    const int kt2 = (nseg > 2) ? (p.K[2] >> 6) : 0;
    const int total = kt0 + kt1 + kt2;

    const uint32_t smBase = (uint32_t)__cvta_generic_to_shared(smem_raw);

    const uint32_t aBase = smBase +
        (uint32_t)(((wm * 64 + (lane & 15)) * PK + ((lane >> 4) << 3)) << 1);
    const uint32_t bBase = smBase + A_BYTES +
        (uint32_t)(((lane & 15) * PN + wn * 32 + ((lane >> 4) << 3)) << 1);

    float acc[4][4][4];
#pragma unroll
    for (int i = 0; i < 4; i++)
#pragma unroll
        for (int j = 0; j < 4; j++)
#pragma unroll
            for (int v = 0; v < 4; v++) acc[i][j][v] = 0.f;

    auto issue = [&](int ti) {
        int s = 0, rem = ti;
        if (rem >= kt0)           { rem -= kt0; s = 1; }
        if (s == 1 && rem >= kt1) { rem -= kt1; s = 2; }
        int k0 = rem * BK;
        const __nv_bfloat16* A = p.A[s];
        const __nv_bfloat16* B = p.B[s];
        int K = p.K[s];
        uint32_t sb = smBase + (uint32_t)((ti % NSTAGE) * STAGE_BYTES);
#pragma unroll
        for (int it = 0; it < 4; it++) {
            int idx = t + it * 256;
            int r   = idx >> 3;
            int c8  = (idx & 7) * 8;
            int gr  = row0 + r;
            bool ok = (gr < M);
            int  sr = ok ? gr : 0;
            uint32_t dst = sb + (uint32_t)((r * PK + c8) << 1);
            cp16(dst, A + (size_t)sr * K + k0 + c8, ok);
        }
#pragma unroll
        for (int it = 0; it < 4; it++) {
            int idx = t + it * 256;
            int kr  = idx >> 4;
            int c8  = (idx & 15) * 8;
            int gc  = col0 + c8;
            bool ok = (gc < Npad);
            int  sc = ok ? gc : 0;
            uint32_t dst = sb + A_BYTES + (uint32_t)((kr * PN + c8) << 1);
            cp16(dst, B + (size_t)(k0 + kr) * Npad + sc, ok);
        }
        asm volatile("cp.async.commit_group;");
    };

    auto load_frags = [&](uint32_t so, int ko, uint32_t (*af)[4], uint32_t (*bf)[4]) {
#pragma unroll
        for (int i = 0; i < 4; i++) {
            uint32_t addr = aBase + so + (uint32_t)(((i * 16) * PK + ko) << 1);
            asm volatile("ldmatrix.sync.aligned.m8n8.x4.shared.b16 {%0,%1,%2,%3}, [%4];"
                         : "=r"(af[i][0]), "=r"(af[i][1]), "=r"(af[i][2]), "=r"(af[i][3])
                         : "r"(addr));
        }
#pragma unroll
        for (int jj = 0; jj < 2; jj++) {
            uint32_t addr = bBase + so + (uint32_t)((ko * PN + jj * 16) << 1);
            asm volatile("ldmatrix.sync.aligned.m8n8.x4.trans.shared.b16 {%0,%1,%2,%3}, [%4];"
                         : "=r"(bf[jj][0]), "=r"(bf[jj][1]), "=r"(bf[jj][2]), "=r"(bf[jj][3])
                         : "r"(addr));
        }
    };

    issue(0);
    if (total > 1) issue(1);

    uint32_t afr[2][4][4];
    uint32_t bfr[2][2][4];

    for (int ti = 0; ti < total; ti++) {
        if (ti + 2 < total) {
            issue(ti + 2);
            asm volatile("cp.async.wait_group 2;");
        } else if (ti + 1 < total) {
            asm volatile("cp.async.wait_group 1;");
        } else {
            asm volatile("cp.async.wait_group 0;");
        }
        __syncthreads();

        const uint32_t so = (uint32_t)((ti % NSTAGE) * STAGE_BYTES);

        load_frags(so, 0, afr[0], bfr[0]);
#pragma unroll
        for (int ks = 0; ks < 4; ks++) {
            const int cur = ks & 1;
            const int nxt = cur ^ 1;
            if (ks < 3) load_frags(so, (ks + 1) * 16, afr[nxt], bfr[nxt]);
#pragma unroll
            for (int i = 0; i < 4; i++)
#pragma unroll
                for (int j = 0; j < 4; j++) {
                    uint32_t b0 = bfr[cur][j >> 1][(j & 1) * 2];
                    uint32_t b1 = bfr[cur][j >> 1][(j & 1) * 2 + 1];
                    asm volatile(
                        "mma.sync.aligned.m16n8k16.row.col.f32.bf16.bf16.f32 "
                        "{%0,%1,%2,%3}, {%4,%5,%6,%7}, {%8,%9}, {%0,%1,%2,%3};\n"
                        : "+f"(acc[i][j][0]), "+f"(acc[i][j][1]),
                          "+f"(acc[i][j][2]), "+f"(acc[i][j][3])
                        : "r"(afr[cur][i][0]), "r"(afr[cur][i][1]),
                          "r"(afr[cur][i][2]), "r"(afr[cur][i][3]),
                          "r"(b0), "r"(b1));
                }
        }
        __syncthreads();
    }

    // ---- staged epilogue: coalesced global stores ----
    __syncthreads();
    if (OUTBF16) {
        __nv_bfloat16* cs = (__nv_bfloat16*)smem_raw;   // [128][136]
        __nv_bfloat16* Cb = (__nv_bfloat16*)p.C;
#pragma unroll
        for (int i = 0; i < 4; i++) {
            int r0l = wm * 64 + i * 16 + g;
#pragma unroll
            for (int j = 0; j < 4; j++) {
                int cl = wn * 32 + j * 8 + tq * 2;
                float bv0 = p.bias[col0 + cl];
                float bv1 = p.bias[col0 + cl + 1];
                float x0 = acc[i][j][0] + bv0, x1 = acc[i][j][1] + bv1;
                float y0 = acc[i][j][2] + bv0, y1 = acc[i][j][3] + bv1;
                if (RELU) {
                    x0 = fmaxf(x0, 0.f); x1 = fmaxf(x1, 0.f);
                    y0 = fmaxf(y0, 0.f); y1 = fmaxf(y1, 0.f);
                }
                *(__nv_bfloat162*)&cs[r0l * 136 + cl]       = __floats2bfloat162_rn(x0, x1);
                *(__nv_bfloat162*)&cs[(r0l + 8) * 136 + cl] = __floats2bfloat162_rn(y0, y1);
            }
        }
        __syncthreads();
#pragma unroll
        for (int it = 0; it < 8; it++) {
            int idx = t + it * 256;
            int r   = idx >> 4;
            int c8  = (idx & 15) * 8;
            int gr  = row0 + r;
            int gc  = col0 + c8;
            if (gr < M) {
                if (gc + 8 <= N) {
                    *(uint4*)&Cb[(size_t)gr * N + gc] = *(uint4*)&cs[r * 136 + c8];
                } else {
                    for (int e = 0; e < 8; e++)
                        if (gc + e < N) Cb[(size_t)gr * N + gc + e] = cs[r * 136 + c8 + e];
                }
            }
        }
    } else {
        float* cs = (float*)smem_raw;   // [64][132] per half
        float* Cf = (float*)p.C;
#pragma unroll
        for (int half = 0; half < 2; half++) {
            __syncthreads();
            if (wm == half) {
#pragma unroll
                for (int i = 0; i < 4; i++) {
                    int r0l = i * 16 + g;
#pragma unroll
                    for (int j = 0; j < 4; j++) {
                        int cl = wn * 32 + j * 8 + tq * 2;
                        float bv0 = p.bias[col0 + cl];
                        float bv1 = p.bias[col0 + cl + 1];
                        cs[r0l * 132 + cl]           = acc[i][j][0] + bv0;
                        cs[r0l * 132 + cl + 1]       = acc[i][j][1] + bv1;
                        cs[(r0l + 8) * 132 + cl]     = acc[i][j][2] + bv0;
                        cs[(r0l + 8) * 132 + cl + 1] = acc[i][j][3] + bv1;
                    }
                }
            }
            __syncthreads();
#pragma unroll
            for (int it = 0; it < 32; it++) {
                int idx = t + it * 256;
                int r   = idx >> 7;
                int c   = idx & 127;
                int gr  = row0 + half * 64 + r;
                int gc  = col0 + c;
                if (gr < M && gc < N)
                    Cf[(size_t)gr * N + gc] = cs[r * 132 + c];
            }
        }
    }
}

template<bool RELU, bool OUTBF16>
__global__ __launch_bounds__(256, 2)
void gemm_fused_kernel(GemmParams p) {
    gemm_body<RELU, OUTBF16>(p, blockIdx.y);
}

// ---------------------------------------------------------------------------
__inline__ __device__ float warpMax(float v) {
#pragma unroll
    for (int o = 16; o; o >>= 1) v = fmaxf(v, __shfl_xor_sync(0xFFFFFFFFu, v, o));
    return v;
}
__inline__ __device__ float warpSum(float v) {
#pragma unroll
    for (int o = 16; o; o >>= 1) v += __shfl_xor_sync(0xFFFFFFFFu, v, o);
    return v;
}

__global__ void log_softmax_kernel(float* __restrict__ x, int N) {
    float* r = x + (size_t)blockIdx.x * N;
    int t = threadIdx.x;

    float m = -1e30f;
    for (int i = t; i < N; i += 128) m = fmaxf(m, r[i]);
    m = warpMax(m);
    __shared__ float shm[4];
    if ((t & 31) == 0) shm[t >> 5] = m;
    __syncthreads();
    m = fmaxf(fmaxf(shm[0], shm[1]), fmaxf(shm[2], shm[3]));

    float s = 0.f;
    for (int i = t; i < N; i += 128) s += expf(r[i] - m);
    s = warpSum(s);
    __shared__ float shs[4];
    if ((t & 31) == 0) shs[t >> 5] = s;
    __syncthreads();
    s = shs[0] + shs[1] + shs[2] + shs[3];

    float lse = m + logf(s);
    for (int i = t; i < N; i += 128) r[i] = r[i] - lse;
}

// ---------------------------------------------------------------------------
extern "C" void kernel_launch(void* const* d_in, const int* in_sizes, int n_in,
                              void* d_out, int out_size) {
    const float* x_paper          = (const float*)d_in[0];
    const float* emb_author       = (const float*)d_in[1];
    const float* lin_paper_w      = (const float*)d_in[2];
    const float* lin_paper_b      = (const float*)d_in[3];
    const float* c0_root_paper_w  = (const float*)d_in[4];
    const float* c0_root_paper_b  = (const float*)d_in[5];
    const float* c0_root_author_w = (const float*)d_in[6];
    const float* c0_root_author_b = (const float*)d_in[7];
    const float* c0_rel_writes_w  = (const float*)d_in[8];
    const float* c0_rel_cites_w   = (const float*)d_in[9];
    const float* c0_rel_revw_w    = (const float*)d_in[10];
    const float* c1_root_w        = (const float*)d_in[11];
    const float* c1_root_b        = (const float*)d_in[12];
    const float* c1_rel_writes_w  = (const float*)d_in[13];
    const float* c1_rel_cites_w   = (const float*)d_in[14];
    const int*   writes_src       = (const int*)d_in[15];
    const int*   writes_dst       = (const int*)d_in[16];
    const int*   cites_src        = (const int*)d_in[17];
    const int*   cites_dst        = (const int*)d_in[18];
    const int*   revw_src         = (const int*)d_in[19];
    const int*   revw_dst         = (const int*)d_in[20];

    const int E_W = in_sizes[15];
    const int E_C = in_sizes[17];
    float* out = (float*)d_out;

    __nv_bfloat16 *hp, *outp, *outa, *aggA, *aggB, *aggC, *aggD, *emba, *xb;
    __nv_bfloat16 *wlin, *w0rp, *w0ra, *w0w, *w0c, *w0r, *w1rt, *w1w, *w1c;
    int *cntW, *cntC, *cntR, *rpW, *rpC, *rpR, *nxW, *nxC, *nxR, *csW, *csC, *csR, *bsum;
    cudaGetSymbolAddress((void**)&hp,   g_hp);
    cudaGetSymbolAddress((void**)&outp, g_outp);
    cudaGetSymbolAddress((void**)&outa, g_outa);
    cudaGetSymbolAddress((void**)&aggA, g_aggA);
    cudaGetSymbolAddress((void**)&aggB, g_aggB);
    cudaGetSymbolAddress((void**)&aggC, g_aggC);
    cudaGetSymbolAddress((void**)&aggD, g_aggD);
    cudaGetSymbolAddress((void**)&emba, g_emba);
    cudaGetSymbolAddress((void**)&xb,   g_xb);
    cudaGetSymbolAddress((void**)&wlin, g_wlin);
    cudaGetSymbolAddress((void**)&w0rp, g_w0rp);
    cudaGetSymbolAddress((void**)&w0ra, g_w0ra);
    cudaGetSymbolAddress((void**)&w0w,  g_w0w);
    cudaGetSymbolAddress((void**)&w0c,  g_w0c);
    cudaGetSymbolAddress((void**)&w0r,  g_w0r);
    cudaGetSymbolAddress((void**)&w1rt, g_w1rt);
    cudaGetSymbolAddress((void**)&w1w,  g_w1w);
    cudaGetSymbolAddress((void**)&w1c,  g_w1c);
    cudaGetSymbolAddress((void**)&cntW, g_cntW);
    cudaGetSymbolAddress((void**)&cntC, g_cntC);
    cudaGetSymbolAddress((void**)&cntR, g_cntR);
    cudaGetSymbolAddress((void**)&rpW,  g_rpW);
    cudaGetSymbolAddress((void**)&rpC,  g_rpC);
    cudaGetSymbolAddress((void**)&rpR,  g_rpR);
    cudaGetSymbolAddress((void**)&nxW,  g_nxW);
    cudaGetSymbolAddress((void**)&nxC,  g_nxC);
    cudaGetSymbolAddress((void**)&nxR,  g_nxR);
    cudaGetSymbolAddress((void**)&csW,  g_csW);
    cudaGetSymbolAddress((void**)&csC,  g_csC);
    cudaGetSymbolAddress((void**)&csR,  g_csR);
    cudaGetSymbolAddress((void**)&bsum, g_bsum);

    cudaFuncSetAttribute(gemm_fused_kernel<false, true >, cudaFuncAttributeMaxDynamicSharedMemorySize, GEMM_SMEM);
    cudaFuncSetAttribute(gemm_fused_kernel<true,  true >, cudaFuncAttributeMaxDynamicSharedMemorySize, GEMM_SMEM);
    cudaFuncSetAttribute(gemm_fused_kernel<false, false>, cudaFuncAttributeMaxDynamicSharedMemorySize, GEMM_SMEM);

    const int tiles_P = (P_N + BM - 1) / BM;   // 782
    const int tiles_A = (A_N + BM - 1) / BM;   // 391

    cudaStream_t s2;
    cudaStreamCreateWithFlags(&s2, cudaStreamNonBlocking);
    cudaEvent_t eFork, eF2B, eCSR, eAggA, eHP, eSide;
    cudaEventCreateWithFlags(&eFork, cudaEventDisableTiming);
    cudaEventCreateWithFlags(&eF2B,  cudaEventDisableTiming);
    cudaEventCreateWithFlags(&eCSR,  cudaEventDisableTiming);
    cudaEventCreateWithFlags(&eAggA, cudaEventDisableTiming);
    cudaEventCreateWithFlags(&eHP,   cudaEventDisableTiming);
    cudaEventCreateWithFlags(&eSide, cudaEventDisableTiming);

    // ---- fork side stream from the capture stream ----
    cudaEventRecord(eFork, 0);
    cudaStreamWaitEvent(s2, eFork, 0);

    // ================= SIDE: CSR chain =================
    {
        int na4 = P_N / 4, nb4 = P_N / 4, nc4 = A_N / 4;
        fill3_kernel<<<(na4 + nb4 + nc4 + 255) / 256, 256, 0, s2>>>(
            (int4*)cntW, na4, (int4*)cntC, nb4, (int4*)cntR, nc4);
    }
    count3_kernel<<<(E_W + E_C + E_W + 255) / 256, 256, 0, s2>>>(
        writes_dst, E_W, cntW, cites_dst, E_C, cntC, revw_dst, E_W, cntR);
    scan1_3_kernel<<<2 * NB_P + NB_A, SCB, 0, s2>>>(cntW, cntC, cntR, bsum);
    scan2_3_kernel<<<1, SCB, 0, s2>>>(bsum);
    scan3_3_kernel<<<2 * NB_P + NB_A, SCB, 0, s2>>>(cntW, cntC, cntR, bsum,
                                                    rpW, rpC, rpR, nxW, nxC, nxR);
    build3_kernel<<<(E_W + E_C + E_W + 255) / 256, 256, 0, s2>>>(
        writes_src, writes_dst, E_W, nxW, csW,
        cites_src, cites_dst, E_C, nxC, csC,
        revw_src, revw_dst, E_W, nxR, csR);
    cudaEventRecord(eCSR, s2);

    // ================= MAIN: conversions + GEMM1 =================
    {
        int n0 = A_N * H_C / 4, n1 = P_N * IN_C / 4;
        f2b_all_kernel<<<(n0 + n1 + 255) / 256, 256>>>(
            (const float4*)emb_author, (uint2*)emba, n0,
            (const float4*)x_paper, (uint2*)xb, n1);
    }
    cudaEventRecord(eF2B, 0);
    {
        W2B b = {};
        const float* srcs[9] = {lin_paper_w, c0_root_paper_w, c0_root_author_w,
                                c0_rel_writes_w, c0_rel_cites_w, c0_rel_revw_w,
                                c1_root_w, c1_rel_writes_w, c1_rel_cites_w};
        __nv_bfloat16* dsts[9] = {wlin, w0rp, w0ra, w0w, w0c, w0r, w1rt, w1w, w1c};
        int Ns[9]    = {H_C, H_C, H_C, H_C, H_C, H_C, OUT_C, OUT_C, OUT_C};
        int Npads[9] = {H_C, H_C, H_C, H_C, H_C, H_C, 352, 352, 352};
        int Ks[9]    = {IN_C, H_C, H_C, H_C, H_C, H_C, H_C, H_C, H_C};
        int cum = 0;
        for (int q = 0; q < 9; q++) {
            b.src[q] = srcs[q]; b.dst[q] = dsts[q];
            b.N[q] = Ns[q]; b.Npad[q] = Npads[q];
            b.cum[q] = cum; cum += Ks[q] * Npads[q];
        }
        b.cum[9] = cum;
        w2b_all_kernel<<<(cum + 255) / 256, 256>>>(b);
    }
    {
        GemmParams p = {};
        p.A[0] = xb; p.B[0] = wlin; p.K[0] = IN_C;
        p.nseg = 1; p.bias = lin_paper_b; p.C = hp; p.M = P_N; p.N = H_C; p.Npad = H_C;
        dim3 grid(H_C / BN, tiles_P);
        gemm_fused_kernel<false, true><<<grid, 256, GEMM_SMEM>>>(p);
    }
    cudaEventRecord(eHP, 0);   // hp + weights ready

    // ================= SIDE: author subgraph =================
    // writes-gather (needs emba + csW)
    cudaStreamWaitEvent(s2, eF2B, 0);
    gather_mean_kernel<<<(P_N + 7) / 8, 256, 0, s2>>>(emba, rpW, csW, P_N, aggA);
    cudaEventRecord(eAggA, s2);
    // revw-gather (needs hp) -> author GEMM -> layer-1 writes-gather
    cudaStreamWaitEvent(s2, eHP, 0);
    gather_mean_kernel<<<(A_N + 7) / 8, 256, 0, s2>>>(hp, rpR, csR, A_N, aggC);
    {
        GemmParams q = {};
        q.A[0] = emba; q.B[0] = w0ra; q.K[0] = H_C;
        q.A[1] = aggC; q.B[1] = w0r;  q.K[1] = H_C;
        q.nseg = 2; q.bias = c0_root_author_b; q.C = outa; q.M = A_N; q.N = H_C; q.Npad = H_C;
        dim3 grid(H_C / BN, tiles_A);
        gemm_fused_kernel<true, true><<<grid, 256, GEMM_SMEM, s2>>>(q);
    }
    gather_mean_kernel<<<(P_N + 7) / 8, 256, 0, s2>>>(outa, rpW, csW, P_N, aggD);
    cudaEventRecord(eSide, s2);

    // ================= MAIN: critical path =================
    cudaStreamWaitEvent(0, eCSR, 0);
    gather_mean_kernel<<<(P_N + 7) / 8, 256>>>(hp, rpC, csC, P_N, aggB);

    cudaStreamWaitEvent(0, eAggA, 0);
    {
        GemmParams p = {};
        p.A[0] = hp;   p.B[0] = w0rp; p.K[0] = H_C;
        p.A[1] = aggA; p.B[1] = w0w;  p.K[1] = H_C;
        p.A[2] = aggB; p.B[2] = w0c;  p.K[2] = H_C;
        p.nseg = 3; p.bias = c0_root_paper_b; p.C = outp; p.M = P_N; p.N = H_C; p.Npad = H_C;
        dim3 grid(H_C / BN, tiles_P);
        gemm_fused_kernel<true, true><<<grid, 256, GEMM_SMEM>>>(p);
    }
    gather_mean_kernel<<<(P_N + 7) / 8, 256>>>(outp, rpC, csC, P_N, aggB);

    // join author subgraph, final GEMM + softmax
    cudaStreamWaitEvent(0, eSide, 0);
    {
        GemmParams p = {};
        p.A[0] = outp; p.B[0] = w1rt; p.K[0] = H_C;
        p.A[1] = aggD; p.B[1] = w1w;  p.K[1] = H_C;
        p.A[2] = aggB; p.B[2] = w1c;  p.K[2] = H_C;
        p.nseg = 3; p.bias = c1_root_b; p.C = out; p.M = P_N; p.N = OUT_C; p.Npad = 352;
        dim3 grid((OUT_C + BN - 1) / BN, tiles_P);
        gemm_fused_kernel<false, false><<<grid, 256, GEMM_SMEM>>>(p);
    }
    log_softmax_kernel<<<P_N, 128>>>(out, OUT_C);
}